// round 6
// baseline (speedup 1.0000x reference)
#include <cuda_runtime.h>
#include <math.h>

#define N_    8192
#define K_    200
#define CIN_  512
#define HID_  256
#define COUT_ 40
#define E_    5
#define MH_   64
#define KG_   40
#define TLUT  4096
#define NS_   16
#define EPS_  1e-5f

// ---------------- device scratch ----------------
__device__ __align__(16) float d_g[E_];
__device__ __align__(16) float d_lut[E_*TLUT];
__device__ __align__(16) float d_vpart[1024*K_];
__device__ __align__(16) float d_Mpart[(size_t)NS_*256*CIN_];
__device__ __align__(16) float d_M[256*CIN_];      // reduced U^T X (rows >=200 unused)
__device__ __align__(16) float d_s[K_];
__device__ __align__(16) float d_P[K_*HID_];
__device__ __align__(16) float d_bnsum[256*HID_];
__device__ __align__(16) float d_bnsq[256*HID_];
__device__ __align__(16) float d_scale[HID_];
__device__ __align__(16) float d_shift[HID_];

// ---------------- tf32 helpers ----------------
__device__ __forceinline__ void split_tf32(float v, float& hi, float& lo){
    unsigned h; asm("cvt.rna.tf32.f32 %0, %1;" : "=r"(h) : "f"(v));
    float hf = __uint_as_float(h);
    float r = v - hf;
    unsigned l; asm("cvt.rna.tf32.f32 %0, %1;" : "=r"(l) : "f"(r));
    hi = hf; lo = __uint_as_float(l);
}

__device__ __forceinline__ void mma_tf32(float* d, const unsigned* a, const unsigned* b){
    asm volatile(
        "mma.sync.aligned.m16n8k8.row.col.f32.tf32.tf32.f32 "
        "{%0,%1,%2,%3},{%4,%5,%6,%7},{%8,%9},{%0,%1,%2,%3};"
        : "+f"(d[0]), "+f"(d[1]), "+f"(d[2]), "+f"(d[3])
        : "r"(a[0]), "r"(a[1]), "r"(a[2]), "r"(a[3]), "r"(b[0]), "r"(b[1]));
}

// ---------------- LUT build + gate (fused) ----------------
__global__ __launch_bounds__(128) void lutgate_kernel(
        const float* __restrict__ eW1, const float* __restrict__ eb1,
        const float* __restrict__ eW2, const float* __restrict__ eb2,
        const float* __restrict__ eW3, const float* __restrict__ eb3,
        const float* __restrict__ La,  const float* __restrict__ gW1,
        const float* __restrict__ gb1, const float* __restrict__ gW2,
        const float* __restrict__ gb2){
    int e = blockIdx.y;
    __shared__ __align__(16) float w2t[MH_*MH_];
    __shared__ float w1[MH_], b1[MH_], b2s[MH_], w3[MH_];
    for (int i = threadIdx.x; i < MH_*MH_; i += blockDim.x){
        int h = i >> 6, g = i & 63;
        w2t[g*MH_ + h] = eW2[(e*MH_ + h)*MH_ + g];
    }
    if (threadIdx.x < MH_){
        int t = threadIdx.x;
        w1[t]  = eW1[e*MH_+t];
        b1[t]  = eb1[e*MH_+t];
        b2s[t] = eb2[e*MH_+t];
        w3[t]  = eW3[e*MH_+t];
    }
    __syncthreads();
    int j = blockIdx.x*blockDim.x + threadIdx.x;
    float u = -8.f + 16.f*(float)j/(float)(TLUT-1);
    float h1[MH_];
    #pragma unroll
    for (int h = 0; h < MH_; h++) h1[h] = fmaxf(fmaf(u, w1[h], b1[h]), 0.f);
    float acc = eb3[e];
    #pragma unroll 2
    for (int g = 0; g < MH_; g++){
        float z = b2s[g];
        const float4* row = (const float4*)(w2t + g*MH_);
        #pragma unroll
        for (int q = 0; q < 16; q++){
            float4 w = row[q];
            z = fmaf(h1[4*q+0], w.x, z);
            z = fmaf(h1[4*q+1], w.y, z);
            z = fmaf(h1[4*q+2], w.z, z);
            z = fmaf(h1[4*q+3], w.w, z);
        }
        acc = fmaf(fmaxf(z, 0.f), w3[g], acc);
    }
    d_lut[e*TLUT + j] = acc;

    if (blockIdx.x == 0 && blockIdx.y == 0 && threadIdx.x == 0){
        float stats[E_];
        for (int ee = 0; ee < E_; ee++){
            float s = 0.f;
            for (int i = 0; i < KG_; i++) s += La[ee*KG_ + i];
            stats[ee] = s / (float)KG_;
        }
        float t1[E_];
        for (int jj = 0; jj < E_; jj++){
            float z = gb1[jj];
            for (int i = 0; i < E_; i++) z += stats[i]*gW1[i*E_+jj];
            t1[jj] = fmaxf(z, 0.f);
        }
        float t2[E_]; float mx = -1e30f;
        for (int jj = 0; jj < E_; jj++){
            float z = gb2[jj];
            for (int i = 0; i < E_; i++) z += t1[i]*gW2[i*E_+jj];
            t2[jj] = z; mx = fmaxf(mx, z);
        }
        float den = 0.f;
        for (int jj = 0; jj < E_; jj++){ t2[jj] = expf(t2[jj]-mx); den += t2[jj]; }
        for (int jj = 0; jj < E_; jj++) d_g[jj] = t2[jj]/den;
    }
}

// ---------------- vs partials: 1024 blocks x 8 rows ----------------
__global__ __launch_bounds__(256) void vs_kernel(const float* __restrict__ U){
    int b = blockIdx.x;
    int col = threadIdx.x;
    if (col >= K_) return;
    int e = col / KG_;
    const float* lut = d_lut + e*TLUT;
    const float invd = (float)(TLUT-1)/16.f;
    float sum = 0.f;
    #pragma unroll
    for (int r = 0; r < 8; r++){
        float u = U[(size_t)(b*8+r)*K_ + col];
        float tt = (u + 8.f)*invd;
        int i = (int)floorf(tt);
        i = min(max(i, 0), TLUT-2);
        float fr = tt - (float)i;
        float a = __ldg(lut + i);
        float bb = __ldg(lut + i + 1);
        sum += a + (bb - a)*fr;
    }
    d_vpart[b*K_ + col] = sum;
}

// ---------------- gemmD: Mpart[z] = U[z]^T @ X[z], 3xTF32, double-buffered ----------------
#define DPAD 136
__global__ __launch_bounds__(256) void gemmD_tc(const float* __restrict__ U, const float* __restrict__ X){
    __shared__ float Ah[2][8][DPAD], Al[2][8][DPAD], Bh[2][8][DPAD], Bl[2][8][DPAD];
    int n0 = blockIdx.x*128;
    int m0 = blockIdx.y*128;
    int rbase = blockIdx.z*512;
    int tid = threadIdx.x;
    int lane = tid & 31, warp = tid >> 5;
    int wm = warp >> 2, wn = warp & 3;
    int g = lane >> 2, t = lane & 3;
    int kk = tid >> 5;
    int c4 = (tid & 31) * 4;
    bool aval = (m0 + c4 < K_);

    float acc[4][4][4];
    #pragma unroll
    for (int i = 0; i < 4; i++)
        #pragma unroll
        for (int j = 0; j < 4; j++){
            acc[i][j][0]=0.f; acc[i][j][1]=0.f; acc[i][j][2]=0.f; acc[i][j][3]=0.f;
        }

    float4 uv, xv;
    auto LOAD = [&](int s){
        int row = rbase + s*8 + kk;
        uv = aval ? *(const float4*)(U + (size_t)row*K_ + m0 + c4)
                  : make_float4(0.f,0.f,0.f,0.f);
        xv = *(const float4*)(X + (size_t)row*CIN_ + n0 + c4);
    };
    auto STORE = [&](int p){
        float h, l;
        split_tf32(uv.x, h, l); Ah[p][kk][c4+0]=h; Al[p][kk][c4+0]=l;
        split_tf32(uv.y, h, l); Ah[p][kk][c4+1]=h; Al[p][kk][c4+1]=l;
        split_tf32(uv.z, h, l); Ah[p][kk][c4+2]=h; Al[p][kk][c4+2]=l;
        split_tf32(uv.w, h, l); Ah[p][kk][c4+3]=h; Al[p][kk][c4+3]=l;
        split_tf32(xv.x, h, l); Bh[p][kk][c4+0]=h; Bl[p][kk][c4+0]=l;
        split_tf32(xv.y, h, l); Bh[p][kk][c4+1]=h; Bl[p][kk][c4+1]=l;
        split_tf32(xv.z, h, l); Bh[p][kk][c4+2]=h; Bl[p][kk][c4+2]=l;
        split_tf32(xv.w, h, l); Bh[p][kk][c4+3]=h; Bl[p][kk][c4+3]=l;
    };

    LOAD(0); STORE(0);
    __syncthreads();

    for (int s = 0; s < 64; s++){
        int p = s & 1;
        if (s < 63) LOAD(s+1);

        unsigned ah[4][4], al[4][4];
        #pragma unroll
        for (int mf = 0; mf < 4; mf++){
            int m = wm*64 + mf*16 + g;
            ah[mf][0] = __float_as_uint(Ah[p][t  ][m  ]);
            ah[mf][1] = __float_as_uint(Ah[p][t  ][m+8]);
            ah[mf][2] = __float_as_uint(Ah[p][t+4][m  ]);
            ah[mf][3] = __float_as_uint(Ah[p][t+4][m+8]);
            al[mf][0] = __float_as_uint(Al[p][t  ][m  ]);
            al[mf][1] = __float_as_uint(Al[p][t  ][m+8]);
            al[mf][2] = __float_as_uint(Al[p][t+4][m  ]);
            al[mf][3] = __float_as_uint(Al[p][t+4][m+8]);
        }
        #pragma unroll
        for (int nf = 0; nf < 4; nf++){
            int n = wn*32 + nf*8 + g;
            unsigned bh[2] = { __float_as_uint(Bh[p][t][n]), __float_as_uint(Bh[p][t+4][n]) };
            unsigned bl[2] = { __float_as_uint(Bl[p][t][n]), __float_as_uint(Bl[p][t+4][n]) };
            #pragma unroll
            for (int mf = 0; mf < 4; mf++){
                mma_tf32(acc[mf][nf], ah[mf], bh);
                mma_tf32(acc[mf][nf], al[mf], bh);
                mma_tf32(acc[mf][nf], ah[mf], bl);
            }
        }
        if (s < 63) STORE(p ^ 1);
        __syncthreads();
    }

    float* out = d_Mpart + (size_t)blockIdx.z*256*CIN_;
    #pragma unroll
    for (int mf = 0; mf < 4; mf++){
        #pragma unroll
        for (int nf = 0; nf < 4; nf++){
            int m = m0 + wm*64 + mf*16 + g;
            int n = n0 + wn*32 + nf*8 + 2*t;
            float2 v0 = make_float2(acc[mf][nf][0], acc[mf][nf][1]);
            float2 v1 = make_float2(acc[mf][nf][2], acc[mf][nf][3]);
            *(float2*)(out + (size_t)m*CIN_ + n)     = v0;
            *(float2*)(out + (size_t)(m+8)*CIN_ + n) = v1;
        }
    }
}

// ---------------- reduceM: d_M = sum_z Mpart, and d_s[k] (fused) ----------------
__global__ __launch_bounds__(256) void reduceM_kernel(){
    int k = blockIdx.x;
    int c = blockIdx.y*256 + threadIdx.x;
    float s = 0.f;
    #pragma unroll
    for (int b = 0; b < NS_; b++) s += d_Mpart[(size_t)b*256*CIN_ + (size_t)k*CIN_ + c];
    d_M[(size_t)k*CIN_ + c] = s;

    if (blockIdx.y == 0){
        __shared__ float red[256];
        float v = 0.f;
        #pragma unroll
        for (int q = 0; q < 4; q++) v += d_vpart[(size_t)(threadIdx.x + q*256)*K_ + k];
        red[threadIdx.x] = v;
        __syncthreads();
        for (int off = 128; off > 0; off >>= 1){
            if (threadIdx.x < off) red[threadIdx.x] += red[threadIdx.x + off];
            __syncthreads();
        }
        if (threadIdx.x == 0) d_s[k] = d_g[k/KG_] * (red[0] / (float)N_);
    }
}

// ---------------- pgemm: P = diag(s) * M @ Ww, 3xTF32, double-buffered ----------------
// tile 64m x 64n; 8 warps (2x4), warp 32x16; K=512 -> 64 stages of 8
#define PPAD 72
__global__ __launch_bounds__(256) void pgemm_tc(const float* __restrict__ Ww){
    __shared__ float Ah[2][8][PPAD], Al[2][8][PPAD], Bh[2][8][PPAD], Bl[2][8][PPAD];
    int n0 = blockIdx.x*64;
    int m0 = blockIdx.y*64;
    int tid = threadIdx.x;
    int lane = tid & 31, warp = tid >> 5;
    int wm = warp >> 2, wn = warp & 3;
    int g = lane >> 2, t = lane & 3;

    // A loader: tid<128 : row=tid>>1 (0..63), q=tid&1
    int arow = tid >> 1, aq = tid & 1;
    bool aval = (m0 + arow < K_);
    // B loader: tid>=128 : kk=(tid-128)>>4, c4=((tid-128)&15)*4
    int bkk = (tid - 128) >> 4, bc4 = ((tid - 128) & 15) * 4;

    float acc[2][2][4];
    #pragma unroll
    for (int i = 0; i < 2; i++)
        #pragma unroll
        for (int j = 0; j < 2; j++){
            acc[i][j][0]=0.f; acc[i][j][1]=0.f; acc[i][j][2]=0.f; acc[i][j][3]=0.f;
        }

    float4 av, bv;
    auto LOAD = [&](int s){
        if (tid < 128)
            av = aval ? *(const float4*)(d_M + (size_t)(m0+arow)*CIN_ + s*8 + aq*4)
                      : make_float4(0.f,0.f,0.f,0.f);
        else
            bv = *(const float4*)(Ww + (size_t)(s*8 + bkk)*HID_ + n0 + bc4);
    };
    auto STORE = [&](int p){
        float h, l;
        if (tid < 128){
            split_tf32(av.x, h, l); Ah[p][aq*4+0][arow]=h; Al[p][aq*4+0][arow]=l;
            split_tf32(av.y, h, l); Ah[p][aq*4+1][arow]=h; Al[p][aq*4+1][arow]=l;
            split_tf32(av.z, h, l); Ah[p][aq*4+2][arow]=h; Al[p][aq*4+2][arow]=l;
            split_tf32(av.w, h, l); Ah[p][aq*4+3][arow]=h; Al[p][aq*4+3][arow]=l;
        } else {
            split_tf32(bv.x, h, l); Bh[p][bkk][bc4+0]=h; Bl[p][bkk][bc4+0]=l;
            split_tf32(bv.y, h, l); Bh[p][bkk][bc4+1]=h; Bl[p][bkk][bc4+1]=l;
            split_tf32(bv.z, h, l); Bh[p][bkk][bc4+2]=h; Bl[p][bkk][bc4+2]=l;
            split_tf32(bv.w, h, l); Bh[p][bkk][bc4+3]=h; Bl[p][bkk][bc4+3]=l;
        }
    };

    LOAD(0); STORE(0);
    __syncthreads();

    for (int s = 0; s < 64; s++){
        int p = s & 1;
        if (s < 63) LOAD(s+1);

        unsigned ah[2][4], al[2][4];
        #pragma unroll
        for (int mf = 0; mf < 2; mf++){
            int m = wm*32 + mf*16 + g;
            ah[mf][0] = __float_as_uint(Ah[p][t  ][m  ]);
            ah[mf][1] = __float_as_uint(Ah[p][t  ][m+8]);
            ah[mf][2] = __float_as_uint(Ah[p][t+4][m  ]);
            ah[mf][3] = __float_as_uint(Ah[p][t+4][m+8]);
            al[mf][0] = __float_as_uint(Al[p][t  ][m  ]);
            al[mf][1] = __float_as_uint(Al[p][t  ][m+8]);
            al[mf][2] = __float_as_uint(Al[p][t+4][m  ]);
            al[mf][3] = __float_as_uint(Al[p][t+4][m+8]);
        }
        #pragma unroll
        for (int nf = 0; nf < 2; nf++){
            int n = wn*16 + nf*8 + g;
            unsigned bh[2] = { __float_as_uint(Bh[p][t][n]), __float_as_uint(Bh[p][t+4][n]) };
            unsigned bl[2] = { __float_as_uint(Bl[p][t][n]), __float_as_uint(Bl[p][t+4][n]) };
            #pragma unroll
            for (int mf = 0; mf < 2; mf++){
                mma_tf32(acc[mf][nf], ah[mf], bh);
                mma_tf32(acc[mf][nf], al[mf], bh);
                mma_tf32(acc[mf][nf], ah[mf], bl);
            }
        }
        if (s < 63) STORE(p ^ 1);
        __syncthreads();
    }

    #pragma unroll
    for (int mf = 0; mf < 2; mf++){
        #pragma unroll
        for (int nf = 0; nf < 2; nf++){
            int m = m0 + wm*32 + mf*16 + g;
            int n = n0 + wn*16 + nf*8 + 2*t;
            if (m < K_){
                float sk = d_s[m];
                float2 v0 = make_float2(acc[mf][nf][0]*sk, acc[mf][nf][1]*sk);
                *(float2*)(d_P + (size_t)m*HID_ + n) = v0;
            }
            if (m + 8 < K_){
                float sk = d_s[m+8];
                float2 v1 = make_float2(acc[mf][nf][2]*sk, acc[mf][nf][3]*sk);
                *(float2*)(d_P + (size_t)(m+8)*HID_ + n) = v1;
            }
        }
    }
}

// ---------------- gemmE: hidden = U @ P + Wb, 3xTF32, double-buffered ----------------
#define EPADA 264
#define EPADB 72
__global__ __launch_bounds__(256) void gemmE_tc(const float* __restrict__ U, const float* __restrict__ Wb,
                                                float* __restrict__ hid){
    __shared__ float Ah[2][8][EPADA], Al[2][8][EPADA], Bh[2][8][EPADB], Bl[2][8][EPADB];
    __shared__ float wbs[64];
    int m0 = blockIdx.x*256;
    int n0 = blockIdx.y*64;
    int tid = threadIdx.x;
    int lane = tid & 31, warp = tid >> 5;
    int wm = warp >> 1, wn = warp & 1;
    int g = lane >> 2, t = lane & 3;
    if (tid < 64) wbs[tid] = Wb[n0 + tid];
    int bkk = tid >> 4;
    int bc4 = (tid & 15) * 4;

    float acc[4][4][4];
    #pragma unroll
    for (int i = 0; i < 4; i++)
        #pragma unroll
        for (int j = 0; j < 4; j++){
            acc[i][j][0]=0.f; acc[i][j][1]=0.f; acc[i][j][2]=0.f; acc[i][j][3]=0.f;
        }

    float4 av0, av1, bv;
    auto LOAD = [&](int s){
        const float* pa = U + (size_t)(m0 + tid)*K_ + s*8;
        av0 = *(const float4*)pa;
        av1 = *(const float4*)(pa + 4);
        if (tid < 128)
            bv = *(const float4*)(d_P + (size_t)(s*8 + bkk)*HID_ + n0 + bc4);
    };
    auto STORE = [&](int p){
        float h, l;
        split_tf32(av0.x, h, l); Ah[p][0][tid]=h; Al[p][0][tid]=l;
        split_tf32(av0.y, h, l); Ah[p][1][tid]=h; Al[p][1][tid]=l;
        split_tf32(av0.z, h, l); Ah[p][2][tid]=h; Al[p][2][tid]=l;
        split_tf32(av0.w, h, l); Ah[p][3][tid]=h; Al[p][3][tid]=l;
        split_tf32(av1.x, h, l); Ah[p][4][tid]=h; Al[p][4][tid]=l;
        split_tf32(av1.y, h, l); Ah[p][5][tid]=h; Al[p][5][tid]=l;
        split_tf32(av1.z, h, l); Ah[p][6][tid]=h; Al[p][6][tid]=l;
        split_tf32(av1.w, h, l); Ah[p][7][tid]=h; Al[p][7][tid]=l;
        if (tid < 128){
            split_tf32(bv.x, h, l); Bh[p][bkk][bc4+0]=h; Bl[p][bkk][bc4+0]=l;
            split_tf32(bv.y, h, l); Bh[p][bkk][bc4+1]=h; Bl[p][bkk][bc4+1]=l;
            split_tf32(bv.z, h, l); Bh[p][bkk][bc4+2]=h; Bl[p][bkk][bc4+2]=l;
            split_tf32(bv.w, h, l); Bh[p][bkk][bc4+3]=h; Bl[p][bkk][bc4+3]=l;
        }
    };

    LOAD(0); STORE(0);
    __syncthreads();

    for (int s = 0; s < 25; s++){
        int p = s & 1;
        if (s < 24) LOAD(s+1);

        unsigned ah[4][4], al[4][4];
        #pragma unroll
        for (int mf = 0; mf < 4; mf++){
            int m = wm*64 + mf*16 + g;
            ah[mf][0] = __float_as_uint(Ah[p][t  ][m  ]);
            ah[mf][1] = __float_as_uint(Ah[p][t  ][m+8]);
            ah[mf][2] = __float_as_uint(Ah[p][t+4][m  ]);
            ah[mf][3] = __float_as_uint(Ah[p][t+4][m+8]);
            al[mf][0] = __float_as_uint(Al[p][t  ][m  ]);
            al[mf][1] = __float_as_uint(Al[p][t  ][m+8]);
            al[mf][2] = __float_as_uint(Al[p][t+4][m  ]);
            al[mf][3] = __float_as_uint(Al[p][t+4][m+8]);
        }
        #pragma unroll
        for (int nf = 0; nf < 4; nf++){
            int n = wn*32 + nf*8 + g;
            unsigned bh[2] = { __float_as_uint(Bh[p][t][n]), __float_as_uint(Bh[p][t+4][n]) };
            unsigned bl[2] = { __float_as_uint(Bl[p][t][n]), __float_as_uint(Bl[p][t+4][n]) };
            #pragma unroll
            for (int mf = 0; mf < 4; mf++){
                mma_tf32(acc[mf][nf], ah[mf], bh);
                mma_tf32(acc[mf][nf], al[mf], bh);
                mma_tf32(acc[mf][nf], ah[mf], bl);
            }
        }
        if (s < 24) STORE(p ^ 1);
        __syncthreads();
    }

    #pragma unroll
    for (int mf = 0; mf < 4; mf++){
        #pragma unroll
        for (int nf = 0; nf < 4; nf++){
            int m = m0 + wm*64 + mf*16 + g;
            int nl = wn*32 + nf*8 + 2*t;
            float2 v0 = make_float2(acc[mf][nf][0] + wbs[nl], acc[mf][nf][1] + wbs[nl+1]);
            float2 v1 = make_float2(acc[mf][nf][2] + wbs[nl], acc[mf][nf][3] + wbs[nl+1]);
            *(float2*)(hid + (size_t)m*HID_ + n0 + nl)     = v0;
            *(float2*)(hid + (size_t)(m+8)*HID_ + n0 + nl) = v1;
        }
    }
}

// ---------------- BN stats ----------------
__global__ __launch_bounds__(256) void bn_partial(const float* __restrict__ hid){
    int j = threadIdx.x;
    int b = blockIdx.x;
    float sum = 0.f, sq = 0.f;
    #pragma unroll 4
    for (int r = 0; r < 32; r++){
        float v = hid[(size_t)(b*32+r)*HID_ + j];
        sum += v; sq = fmaf(v, v, sq);
    }
    d_bnsum[b*HID_ + j] = sum;
    d_bnsq [b*HID_ + j] = sq;
}

__global__ void bn_final(const float* __restrict__ gamma, const float* __restrict__ beta){
    int j = threadIdx.x;
    float sum = 0.f, sq = 0.f;
    for (int s = 0; s < 256; s++){ sum += d_bnsum[s*HID_+j]; sq += d_bnsq[s*HID_+j]; }
    float mu  = sum / (float)N_;
    float var = sq / (float)N_ - mu*mu;
    float sc  = gamma[j] * rsqrtf(var + EPS_);
    d_scale[j] = sc;
    d_shift[j] = beta[j] - mu*sc;
}

// ---------------- head: 16 rows per block ----------------
__global__ __launch_bounds__(256) void final_kernel(const float* __restrict__ hid,
                                                    const float* __restrict__ Mw,
                                                    const float* __restrict__ Mb,
                                                    float* __restrict__ logits_out){
    __shared__ float h[16*260];
    __shared__ float lg[16*COUT_];
    __shared__ float lz[16];
    int r0 = blockIdx.x * 16;
    int tid = threadIdx.x;
    #pragma unroll
    for (int r = 0; r < 16; r++){
        float v = hid[(size_t)(r0+r)*HID_ + tid];
        h[r*260 + tid] = fmaxf(fmaf(v, d_scale[tid], d_shift[tid]), 0.f);
    }
    __syncthreads();
    for (int base = 0; base < 16*COUT_; base += 256){
        int idx = base + tid;
        if (idx < 16*COUT_){
            int row = idx / COUT_;
            int o   = idx - row*COUT_;
            float a = Mb[o];
            #pragma unroll 4
            for (int c = 0; c < HID_; c++)
                a = fmaf(h[row*260 + c], Mw[c*COUT_ + o], a);
            lg[idx] = a;
        }
    }
    __syncthreads();
    if (tid < 16){
        float mx = -1e30f;
        for (int o = 0; o < COUT_; o++) mx = fmaxf(mx, lg[tid*COUT_+o]);
        float s = 0.f;
        for (int o = 0; o < COUT_; o++) s += expf(lg[tid*COUT_+o]-mx);
        lz[tid] = mx + logf(s);
    }
    __syncthreads();
    for (int base = 0; base < 16*COUT_; base += 256){
        int idx = base + tid;
        if (idx < 16*COUT_){
            int row = idx / COUT_;
            logits_out[(size_t)r0*COUT_ + idx] = lg[idx] - lz[row];
        }
    }
}

// ---------------- launch ----------------
extern "C" void kernel_launch(void* const* d_in, const int* in_sizes, int n_in,
                              void* d_out, int out_size){
    const float* X     = (const float*)d_in[0];
    const float* La    = (const float*)d_in[1];
    const float* U     = (const float*)d_in[2];
    const float* eW1   = (const float*)d_in[3];
    const float* eb1   = (const float*)d_in[4];
    const float* eW2   = (const float*)d_in[5];
    const float* eb2   = (const float*)d_in[6];
    const float* eW3   = (const float*)d_in[7];
    const float* eb3   = (const float*)d_in[8];
    const float* gW1   = (const float*)d_in[9];
    const float* gb1   = (const float*)d_in[10];
    const float* gW2   = (const float*)d_in[11];
    const float* gb2   = (const float*)d_in[12];
    const float* Ww    = (const float*)d_in[13];
    const float* Wb    = (const float*)d_in[14];
    const float* gamma = (const float*)d_in[15];
    const float* beta  = (const float*)d_in[16];
    const float* Mw    = (const float*)d_in[17];
    const float* Mb    = (const float*)d_in[18];

    float* outF   = (float*)d_out;
    float* logits = outF;                              // [N, COUT]
    float* hidden = outF + (size_t)N_*COUT_;           // [N, HID]

    lutgate_kernel<<<dim3(TLUT/128, E_), 128>>>(eW1, eb1, eW2, eb2, eW3, eb3,
                                                La, gW1, gb1, gW2, gb2);
    gemmD_tc<<<dim3(CIN_/128, 2, NS_), 256>>>(U, X);
    vs_kernel<<<1024, 256>>>(U);
    reduceM_kernel<<<dim3(K_, 2), 256>>>();
    pgemm_tc<<<dim3(HID_/64, 4), 256>>>(Ww);
    gemmE_tc<<<dim3(N_/256, HID_/64), 256>>>(U, Wb, hidden);
    bn_partial<<<256, 256>>>(hidden);
    bn_final<<<1, HID_>>>(gamma, beta);
    final_kernel<<<N_/16, 256>>>(hidden, Mw, Mb, logits);
}

// round 9
// speedup vs baseline: 1.0439x; 1.0439x over previous
#include <cuda_runtime.h>
#include <math.h>

#define N_    8192
#define K_    200
#define CIN_  512
#define HID_  256
#define COUT_ 40
#define E_    5
#define MH_   64
#define KG_   40
#define TLUT  4096
#define NS2   32
#define PZ    8
#define EPS_  1e-5f

// ---------------- device scratch ----------------
__device__ __align__(16) float d_g[E_];
__device__ __align__(16) float d_lut[E_*TLUT];
__device__ __align__(16) float d_vpart[1024*K_];
__device__ __align__(16) float d_Mpart[(size_t)NS2*256*CIN_];
__device__ __align__(16) float d_M[256*CIN_];
__device__ __align__(16) float d_s[K_];
__device__ __align__(16) float d_Ppart[(size_t)PZ*256*HID_];
__device__ __align__(16) float d_bnsum[256*HID_];
__device__ __align__(16) float d_bnsq[256*HID_];
__device__ __align__(16) float d_scale[HID_];
__device__ __align__(16) float d_shift[HID_];

// ---------------- tf32 helpers ----------------
__device__ __forceinline__ void split_tf32(float v, float& hi, float& lo){
    unsigned h; asm("cvt.rna.tf32.f32 %0, %1;" : "=r"(h) : "f"(v));
    float hf = __uint_as_float(h);
    float r = v - hf;
    unsigned l; asm("cvt.rna.tf32.f32 %0, %1;" : "=r"(l) : "f"(r));
    hi = hf; lo = __uint_as_float(l);
}

__device__ __forceinline__ void mma_tf32(float* d, const unsigned* a, const unsigned* b){
    asm volatile(
        "mma.sync.aligned.m16n8k8.row.col.f32.tf32.tf32.f32 "
        "{%0,%1,%2,%3},{%4,%5,%6,%7},{%8,%9},{%0,%1,%2,%3};"
        : "+f"(d[0]), "+f"(d[1]), "+f"(d[2]), "+f"(d[3])
        : "r"(a[0]), "r"(a[1]), "r"(a[2]), "r"(a[3]), "r"(b[0]), "r"(b[1]));
}

// ---------------- gate ----------------
__global__ void gate_kernel(const float* __restrict__ La, const float* __restrict__ gW1,
                            const float* __restrict__ gb1, const float* __restrict__ gW2,
                            const float* __restrict__ gb2){
    if (threadIdx.x != 0) return;
    float stats[E_];
    for (int e = 0; e < E_; e++){
        float s = 0.f;
        for (int i = 0; i < KG_; i++) s += La[e*KG_ + i];
        stats[e] = s / (float)KG_;
    }
    float t1[E_];
    for (int j = 0; j < E_; j++){
        float z = gb1[j];
        for (int i = 0; i < E_; i++) z += stats[i]*gW1[i*E_+j];
        t1[j] = fmaxf(z, 0.f);
    }
    float t2[E_]; float mx = -1e30f;
    for (int j = 0; j < E_; j++){
        float z = gb2[j];
        for (int i = 0; i < E_; i++) z += t1[i]*gW2[i*E_+j];
        t2[j] = z; mx = fmaxf(mx, z);
    }
    float den = 0.f;
    for (int j = 0; j < E_; j++){ t2[j] = expf(t2[j]-mx); den += t2[j]; }
    for (int j = 0; j < E_; j++) d_g[j] = t2[j]/den;
}

// ---------------- LUT build ----------------
__global__ __launch_bounds__(128) void lut_kernel(
        const float* __restrict__ eW1, const float* __restrict__ eb1,
        const float* __restrict__ eW2, const float* __restrict__ eb2,
        const float* __restrict__ eW3, const float* __restrict__ eb3){
    int e = blockIdx.y;
    __shared__ __align__(16) float w2t[MH_*MH_];
    __shared__ float w1[MH_], b1[MH_], b2s[MH_], w3[MH_];
    for (int i = threadIdx.x; i < MH_*MH_; i += blockDim.x){
        int h = i >> 6, g = i & 63;
        w2t[g*MH_ + h] = eW2[(e*MH_ + h)*MH_ + g];
    }
    if (threadIdx.x < MH_){
        int t = threadIdx.x;
        w1[t]  = eW1[e*MH_+t];
        b1[t]  = eb1[e*MH_+t];
        b2s[t] = eb2[e*MH_+t];
        w3[t]  = eW3[e*MH_+t];
    }
    __syncthreads();
    int j = blockIdx.x*blockDim.x + threadIdx.x;
    float u = -8.f + 16.f*(float)j/(float)(TLUT-1);
    float h1[MH_];
    #pragma unroll
    for (int h = 0; h < MH_; h++) h1[h] = fmaxf(fmaf(u, w1[h], b1[h]), 0.f);
    float acc = eb3[e];
    #pragma unroll 2
    for (int g = 0; g < MH_; g++){
        float z = b2s[g];
        const float4* row = (const float4*)(w2t + g*MH_);
        #pragma unroll
        for (int q = 0; q < 16; q++){
            float4 w = row[q];
            z = fmaf(h1[4*q+0], w.x, z);
            z = fmaf(h1[4*q+1], w.y, z);
            z = fmaf(h1[4*q+2], w.z, z);
            z = fmaf(h1[4*q+3], w.w, z);
        }
        acc = fmaf(fmaxf(z, 0.f), w3[g], acc);
    }
    d_lut[e*TLUT + j] = acc;
}

// ---------------- vs partials ----------------
__global__ __launch_bounds__(256) void vs_kernel(const float* __restrict__ U){
    int b = blockIdx.x;
    int col = threadIdx.x;
    if (col >= K_) return;
    int e = col / KG_;
    const float* lut = d_lut + e*TLUT;
    const float invd = (float)(TLUT-1)/16.f;
    float sum = 0.f;
    #pragma unroll
    for (int r = 0; r < 8; r++){
        float u = U[(size_t)(b*8+r)*K_ + col];
        float tt = (u + 8.f)*invd;
        int i = (int)floorf(tt);
        i = min(max(i, 0), TLUT-2);
        float fr = tt - (float)i;
        float a = __ldg(lut + i);
        float bb = __ldg(lut + i + 1);
        sum += a + (bb - a)*fr;
    }
    d_vpart[b*K_ + col] = sum;
}

// ---------------- gemmD: Mpart[z] = U[z]^T @ X[z]; tile 128m x 64n; 512 blocks ----------------
#define DPA 136
#define DPB 72
__global__ __launch_bounds__(256) void gemmD_tc(const float* __restrict__ U, const float* __restrict__ X){
    __shared__ float Ah[2][8][DPA], Al[2][8][DPA], Bh[2][8][DPB], Bl[2][8][DPB];
    int n0 = blockIdx.x*64;          // 8
    int m0 = blockIdx.y*128;         // 2
    int rbase = blockIdx.z*256;      // 32
    int tid = threadIdx.x;
    int lane = tid & 31, warp = tid >> 5;
    int wm = warp >> 1, wn = warp & 1;   // 4 x 2 warps, warp tile 32x32
    int g = lane >> 2, t = lane & 3;
    int kk = tid >> 5,  c4  = (tid & 31) * 4;    // A loader (all 256)
    int bkk = tid >> 4, bc4 = (tid & 15) * 4;    // B loader (tid<128)
    bool aval = (m0 + c4 < K_);

    float acc[2][4][4];
    #pragma unroll
    for (int i = 0; i < 2; i++)
        #pragma unroll
        for (int j = 0; j < 4; j++){
            acc[i][j][0]=0.f; acc[i][j][1]=0.f; acc[i][j][2]=0.f; acc[i][j][3]=0.f;
        }

    float4 uv, xv;
    auto LOAD = [&](int s){
        int row = rbase + s*8;
        uv = aval ? *(const float4*)(U + (size_t)(row+kk)*K_ + m0 + c4)
                  : make_float4(0.f,0.f,0.f,0.f);
        if (tid < 128) xv = *(const float4*)(X + (size_t)(row+bkk)*CIN_ + n0 + bc4);
    };
    auto STORE = [&](int p){
        float h, l;
        split_tf32(uv.x, h, l); Ah[p][kk][c4+0]=h; Al[p][kk][c4+0]=l;
        split_tf32(uv.y, h, l); Ah[p][kk][c4+1]=h; Al[p][kk][c4+1]=l;
        split_tf32(uv.z, h, l); Ah[p][kk][c4+2]=h; Al[p][kk][c4+2]=l;
        split_tf32(uv.w, h, l); Ah[p][kk][c4+3]=h; Al[p][kk][c4+3]=l;
        if (tid < 128){
            split_tf32(xv.x, h, l); Bh[p][bkk][bc4+0]=h; Bl[p][bkk][bc4+0]=l;
            split_tf32(xv.y, h, l); Bh[p][bkk][bc4+1]=h; Bl[p][bkk][bc4+1]=l;
            split_tf32(xv.z, h, l); Bh[p][bkk][bc4+2]=h; Bl[p][bkk][bc4+2]=l;
            split_tf32(xv.w, h, l); Bh[p][bkk][bc4+3]=h; Bl[p][bkk][bc4+3]=l;
        }
    };

    LOAD(0); STORE(0);
    __syncthreads();

    for (int s = 0; s < 32; s++){
        int p = s & 1;
        if (s < 31) LOAD(s+1);

        unsigned ah[2][4], al[2][4];
        #pragma unroll
        for (int mf = 0; mf < 2; mf++){
            int m = wm*32 + mf*16 + g;
            ah[mf][0] = __float_as_uint(Ah[p][t  ][m  ]);
            ah[mf][1] = __float_as_uint(Ah[p][t  ][m+8]);
            ah[mf][2] = __float_as_uint(Ah[p][t+4][m  ]);
            ah[mf][3] = __float_as_uint(Ah[p][t+4][m+8]);
            al[mf][0] = __float_as_uint(Al[p][t  ][m  ]);
            al[mf][1] = __float_as_uint(Al[p][t  ][m+8]);
            al[mf][2] = __float_as_uint(Al[p][t+4][m  ]);
            al[mf][3] = __float_as_uint(Al[p][t+4][m+8]);
        }
        #pragma unroll
        for (int nf = 0; nf < 4; nf++){
            int n = wn*32 + nf*8 + g;
            unsigned bh[2] = { __float_as_uint(Bh[p][t][n]), __float_as_uint(Bh[p][t+4][n]) };
            unsigned bl[2] = { __float_as_uint(Bl[p][t][n]), __float_as_uint(Bl[p][t+4][n]) };
            #pragma unroll
            for (int mf = 0; mf < 2; mf++){
                mma_tf32(acc[mf][nf], ah[mf], bh);
                mma_tf32(acc[mf][nf], al[mf], bh);
                mma_tf32(acc[mf][nf], ah[mf], bl);
            }
        }
        if (s < 31) STORE(p ^ 1);
        __syncthreads();
    }

    float* out = d_Mpart + (size_t)blockIdx.z*256*CIN_;
    #pragma unroll
    for (int mf = 0; mf < 2; mf++){
        #pragma unroll
        for (int nf = 0; nf < 4; nf++){
            int m = m0 + wm*32 + mf*16 + g;
            int n = n0 + wn*32 + nf*8 + 2*t;
            *(float2*)(out + (size_t)m*CIN_ + n)     = make_float2(acc[mf][nf][0], acc[mf][nf][1]);
            *(float2*)(out + (size_t)(m+8)*CIN_ + n) = make_float2(acc[mf][nf][2], acc[mf][nf][3]);
        }
    }
}

// ---------------- reduceM: d_M = sum_z Mpart, and d_s[k] ----------------
__global__ __launch_bounds__(256) void reduceM_kernel(){
    int k = blockIdx.x;
    int c = blockIdx.y*256 + threadIdx.x;
    float s = 0.f;
    #pragma unroll
    for (int b = 0; b < NS2; b++) s += d_Mpart[(size_t)b*256*CIN_ + (size_t)k*CIN_ + c];
    d_M[(size_t)k*CIN_ + c] = s;

    if (blockIdx.y == 0){
        __shared__ float red[256];
        float v = 0.f;
        #pragma unroll
        for (int q = 0; q < 4; q++) v += d_vpart[(size_t)(threadIdx.x + q*256)*K_ + k];
        red[threadIdx.x] = v;
        __syncthreads();
        for (int off = 128; off > 0; off >>= 1){
            if (threadIdx.x < off) red[threadIdx.x] += red[threadIdx.x + off];
            __syncthreads();
        }
        if (threadIdx.x == 0) d_s[k] = d_g[k/KG_] * (red[0] / (float)N_);
    }
}

// ---------------- pgemm split-K: Ppart[z] = M[:,z*64:(z+1)*64] @ Ww[z*64:(z+1)*64,:] ----------------
#define PPAD 72
__global__ __launch_bounds__(256) void pgemm_tc(const float* __restrict__ Ww){
    __shared__ float Ah[2][8][PPAD], Al[2][8][PPAD], Bh[2][8][PPAD], Bl[2][8][PPAD];
    int n0 = blockIdx.x*64;
    int m0 = blockIdx.y*64;
    int z  = blockIdx.z;
    int tid = threadIdx.x;
    int lane = tid & 31, warp = tid >> 5;
    int wm = warp >> 2, wn = warp & 3;
    int g = lane >> 2, t = lane & 3;

    int arow = tid >> 1, aq = tid & 1;
    bool aval = (m0 + arow < K_);
    int bkk = (tid - 128) >> 4, bc4 = ((tid - 128) & 15) * 4;

    float acc[2][2][4];
    #pragma unroll
    for (int i = 0; i < 2; i++)
        #pragma unroll
        for (int j = 0; j < 2; j++){
            acc[i][j][0]=0.f; acc[i][j][1]=0.f; acc[i][j][2]=0.f; acc[i][j][3]=0.f;
        }

    float4 av, bv;
    auto LOAD = [&](int s){
        if (tid < 128)
            av = aval ? *(const float4*)(d_M + (size_t)(m0+arow)*CIN_ + z*64 + s*8 + aq*4)
                      : make_float4(0.f,0.f,0.f,0.f);
        else
            bv = *(const float4*)(Ww + (size_t)(z*64 + s*8 + bkk)*HID_ + n0 + bc4);
    };
    auto STORE = [&](int p){
        float h, l;
        if (tid < 128){
            split_tf32(av.x, h, l); Ah[p][aq*4+0][arow]=h; Al[p][aq*4+0][arow]=l;
            split_tf32(av.y, h, l); Ah[p][aq*4+1][arow]=h; Al[p][aq*4+1][arow]=l;
            split_tf32(av.z, h, l); Ah[p][aq*4+2][arow]=h; Al[p][aq*4+2][arow]=l;
            split_tf32(av.w, h, l); Ah[p][aq*4+3][arow]=h; Al[p][aq*4+3][arow]=l;
        } else {
            split_tf32(bv.x, h, l); Bh[p][bkk][bc4+0]=h; Bl[p][bkk][bc4+0]=l;
            split_tf32(bv.y, h, l); Bh[p][bkk][bc4+1]=h; Bl[p][bkk][bc4+1]=l;
            split_tf32(bv.z, h, l); Bh[p][bkk][bc4+2]=h; Bl[p][bkk][bc4+2]=l;
            split_tf32(bv.w, h, l); Bh[p][bkk][bc4+3]=h; Bl[p][bkk][bc4+3]=l;
        }
    };

    LOAD(0); STORE(0);
    __syncthreads();

    for (int s = 0; s < 8; s++){
        int p = s & 1;
        if (s < 7) LOAD(s+1);

        unsigned ah[2][4], al[2][4];
        #pragma unroll
        for (int mf = 0; mf < 2; mf++){
            int m = wm*32 + mf*16 + g;
            ah[mf][0] = __float_as_uint(Ah[p][t  ][m  ]);
            ah[mf][1] = __float_as_uint(Ah[p][t  ][m+8]);
            ah[mf][2] = __float_as_uint(Ah[p][t+4][m  ]);
            ah[mf][3] = __float_as_uint(Ah[p][t+4][m+8]);
            al[mf][0] = __float_as_uint(Al[p][t  ][m  ]);
            al[mf][1] = __float_as_uint(Al[p][t  ][m+8]);
            al[mf][2] = __float_as_uint(Al[p][t+4][m  ]);
            al[mf][3] = __float_as_uint(Al[p][t+4][m+8]);
        }
        #pragma unroll
        for (int nf = 0; nf < 2; nf++){
            int n = wn*16 + nf*8 + g;
            unsigned bh[2] = { __float_as_uint(Bh[p][t][n]), __float_as_uint(Bh[p][t+4][n]) };
            unsigned bl[2] = { __float_as_uint(Bl[p][t][n]), __float_as_uint(Bl[p][t+4][n]) };
            #pragma unroll
            for (int mf = 0; mf < 2; mf++){
                mma_tf32(acc[mf][nf], ah[mf], bh);
                mma_tf32(acc[mf][nf], al[mf], bh);
                mma_tf32(acc[mf][nf], ah[mf], bl);
            }
        }
        if (s < 7) STORE(p ^ 1);
        __syncthreads();
    }

    float* out = d_Ppart + (size_t)z*256*HID_;
    #pragma unroll
    for (int mf = 0; mf < 2; mf++){
        #pragma unroll
        for (int nf = 0; nf < 2; nf++){
            int m = m0 + wm*32 + mf*16 + g;
            int n = n0 + wn*16 + nf*8 + 2*t;
            if (m < K_)
                *(float2*)(out + (size_t)m*HID_ + n) = make_float2(acc[mf][nf][0], acc[mf][nf][1]);
            if (m + 8 < K_)
                *(float2*)(out + (size_t)(m+8)*HID_ + n) = make_float2(acc[mf][nf][2], acc[mf][nf][3]);
        }
    }
}

// ---------------- gemmE: hidden = U @ (s*sum_z Ppart) + Wb; tile 128m x 64n; 256 blocks ----------------
#define EPA 136
#define EPB 72
__global__ __launch_bounds__(256) void gemmE_tc(const float* __restrict__ U, const float* __restrict__ Wb,
                                                float* __restrict__ hid){
    __shared__ float Ah[2][8][EPA], Al[2][8][EPA], Bh[2][8][EPB], Bl[2][8][EPB];
    __shared__ float wbs[64];
    int m0 = blockIdx.x*128;     // 64
    int n0 = blockIdx.y*64;      // 4
    int tid = threadIdx.x;
    int lane = tid & 31, warp = tid >> 5;
    int wm = warp >> 1, wn = warp & 1;   // 4x2 warps, 32x32 tile
    int g = lane >> 2, t = lane & 3;
    if (tid < 64) wbs[tid] = Wb[n0 + tid];
    int arow = tid >> 1, aq = tid & 1;   // A loader (all)
    int bkk = tid >> 4, bc4 = (tid & 15) * 4;  // B loader (tid<128)

    float acc[2][4][4];
    #pragma unroll
    for (int i = 0; i < 2; i++)
        #pragma unroll
        for (int j = 0; j < 4; j++){
            acc[i][j][0]=0.f; acc[i][j][1]=0.f; acc[i][j][2]=0.f; acc[i][j][3]=0.f;
        }

    float4 av, bv;
    auto LOAD = [&](int s){
        av = *(const float4*)(U + (size_t)(m0+arow)*K_ + s*8 + aq*4);
        if (tid < 128){
            int k = s*8 + bkk;
            size_t off = (size_t)k*HID_ + n0 + bc4;
            float4 b0 = *(const float4*)(d_Ppart + off);
            #pragma unroll
            for (int zz = 1; zz < PZ; zz++){
                float4 bz = *(const float4*)(d_Ppart + (size_t)zz*256*HID_ + off);
                b0.x += bz.x; b0.y += bz.y; b0.z += bz.z; b0.w += bz.w;
            }
            float sk = d_s[k];
            bv = make_float4(b0.x*sk, b0.y*sk, b0.z*sk, b0.w*sk);
        }
    };
    auto STORE = [&](int p){
        float h, l;
        split_tf32(av.x, h, l); Ah[p][aq*4+0][arow]=h; Al[p][aq*4+0][arow]=l;
        split_tf32(av.y, h, l); Ah[p][aq*4+1][arow]=h; Al[p][aq*4+1][arow]=l;
        split_tf32(av.z, h, l); Ah[p][aq*4+2][arow]=h; Al[p][aq*4+2][arow]=l;
        split_tf32(av.w, h, l); Ah[p][aq*4+3][arow]=h; Al[p][aq*4+3][arow]=l;
        if (tid < 128){
            split_tf32(bv.x, h, l); Bh[p][bkk][bc4+0]=h; Bl[p][bkk][bc4+0]=l;
            split_tf32(bv.y, h, l); Bh[p][bkk][bc4+1]=h; Bl[p][bkk][bc4+1]=l;
            split_tf32(bv.z, h, l); Bh[p][bkk][bc4+2]=h; Bl[p][bkk][bc4+2]=l;
            split_tf32(bv.w, h, l); Bh[p][bkk][bc4+3]=h; Bl[p][bkk][bc4+3]=l;
        }
    };

    LOAD(0); STORE(0);
    __syncthreads();

    for (int s = 0; s < 25; s++){
        int p = s & 1;
        if (s < 24) LOAD(s+1);

        unsigned ah[2][4], al[2][4];
        #pragma unroll
        for (int mf = 0; mf < 2; mf++){
            int m = wm*32 + mf*16 + g;
            ah[mf][0] = __float_as_uint(Ah[p][t  ][m  ]);
            ah[mf][1] = __float_as_uint(Ah[p][t  ][m+8]);
            ah[mf][2] = __float_as_uint(Ah[p][t+4][m  ]);
            ah[mf][3] = __float_as_uint(Ah[p][t+4][m+8]);
            al[mf][0] = __float_as_uint(Al[p][t  ][m  ]);
            al[mf][1] = __float_as_uint(Al[p][t  ][m+8]);
            al[mf][2] = __float_as_uint(Al[p][t+4][m  ]);
            al[mf][3] = __float_as_uint(Al[p][t+4][m+8]);
        }
        #pragma unroll
        for (int nf = 0; nf < 4; nf++){
            int n = wn*32 + nf*8 + g;
            unsigned bh[2] = { __float_as_uint(Bh[p][t][n]), __float_as_uint(Bh[p][t+4][n]) };
            unsigned bl[2] = { __float_as_uint(Bl[p][t][n]), __float_as_uint(Bl[p][t+4][n]) };
            #pragma unroll
            for (int mf = 0; mf < 2; mf++){
                mma_tf32(acc[mf][nf], ah[mf], bh);
                mma_tf32(acc[mf][nf], al[mf], bh);
                mma_tf32(acc[mf][nf], ah[mf], bl);
            }
        }
        if (s < 24) STORE(p ^ 1);
        __syncthreads();
    }

    #pragma unroll
    for (int mf = 0; mf < 2; mf++){
        #pragma unroll
        for (int nf = 0; nf < 4; nf++){
            int m = m0 + wm*32 + mf*16 + g;
            int nl = wn*32 + nf*8 + 2*t;
            float2 v0 = make_float2(acc[mf][nf][0] + wbs[nl], acc[mf][nf][1] + wbs[nl+1]);
            float2 v1 = make_float2(acc[mf][nf][2] + wbs[nl], acc[mf][nf][3] + wbs[nl+1]);
            *(float2*)(hid + (size_t)m*HID_ + n0 + nl)     = v0;
            *(float2*)(hid + (size_t)(m+8)*HID_ + n0 + nl) = v1;
        }
    }
}

// ---------------- BN stats ----------------
__global__ __launch_bounds__(256) void bn_partial(const float* __restrict__ hid){
    int j = threadIdx.x;
    int b = blockIdx.x;
    float sum = 0.f, sq = 0.f;
    #pragma unroll 4
    for (int r = 0; r < 32; r++){
        float v = hid[(size_t)(b*32+r)*HID_ + j];
        sum += v; sq = fmaf(v, v, sq);
    }
    d_bnsum[b*HID_ + j] = sum;
    d_bnsq [b*HID_ + j] = sq;
}

__global__ void bn_final(const float* __restrict__ gamma, const float* __restrict__ beta){
    int j = threadIdx.x;
    float sum = 0.f, sq = 0.f;
    for (int s = 0; s < 256; s++){ sum += d_bnsum[s*HID_+j]; sq += d_bnsq[s*HID_+j]; }
    float mu  = sum / (float)N_;
    float var = sq / (float)N_ - mu*mu;
    float sc  = gamma[j] * rsqrtf(var + EPS_);
    d_scale[j] = sc;
    d_shift[j] = beta[j] - mu*sc;
}

// ---------------- head: 16 rows per block ----------------
__global__ __launch_bounds__(256) void final_kernel(const float* __restrict__ hid,
                                                    const float* __restrict__ Mw,
                                                    const float* __restrict__ Mb,
                                                    float* __restrict__ logits_out){
    __shared__ float h[16*260];
    __shared__ float lg[16*COUT_];
    __shared__ float lz[16];
    int r0 = blockIdx.x * 16;
    int tid = threadIdx.x;
    #pragma unroll
    for (int r = 0; r < 16; r++){
        float v = hid[(size_t)(r0+r)*HID_ + tid];
        h[r*260 + tid] = fmaxf(fmaf(v, d_scale[tid], d_shift[tid]), 0.f);
    }
    __syncthreads();
    for (int base = 0; base < 16*COUT_; base += 256){
        int idx = base + tid;
        if (idx < 16*COUT_){
            int row = idx / COUT_;
            int o   = idx - row*COUT_;
            float a = Mb[o];
            #pragma unroll 4
            for (int c = 0; c < HID_; c++)
                a = fmaf(h[row*260 + c], Mw[c*COUT_ + o], a);
            lg[idx] = a;
        }
    }
    __syncthreads();
    if (tid < 16){
        float mx = -1e30f;
        for (int o = 0; o < COUT_; o++) mx = fmaxf(mx, lg[tid*COUT_+o]);
        float s = 0.f;
        for (int o = 0; o < COUT_; o++) s += expf(lg[tid*COUT_+o]-mx);
        lz[tid] = mx + logf(s);
    }
    __syncthreads();
    for (int base = 0; base < 16*COUT_; base += 256){
        int idx = base + tid;
        if (idx < 16*COUT_){
            int row = idx / COUT_;
            logits_out[(size_t)r0*COUT_ + idx] = lg[idx] - lz[row];
        }
    }
}

// ---------------- launch ----------------
extern "C" void kernel_launch(void* const* d_in, const int* in_sizes, int n_in,
                              void* d_out, int out_size){
    const float* X     = (const float*)d_in[0];
    const float* La    = (const float*)d_in[1];
    const float* U     = (const float*)d_in[2];
    const float* eW1   = (const float*)d_in[3];
    const float* eb1   = (const float*)d_in[4];
    const float* eW2   = (const float*)d_in[5];
    const float* eb2   = (const float*)d_in[6];
    const float* eW3   = (const float*)d_in[7];
    const float* eb3   = (const float*)d_in[8];
    const float* gW1   = (const float*)d_in[9];
    const float* gb1   = (const float*)d_in[10];
    const float* gW2   = (const float*)d_in[11];
    const float* gb2   = (const float*)d_in[12];
    const float* Ww    = (const float*)d_in[13];
    const float* Wb    = (const float*)d_in[14];
    const float* gamma = (const float*)d_in[15];
    const float* beta  = (const float*)d_in[16];
    const float* Mw    = (const float*)d_in[17];
    const float* Mb    = (const float*)d_in[18];

    float* outF   = (float*)d_out;
    float* logits = outF;                              // [N, COUT]
    float* hidden = outF + (size_t)N_*COUT_;           // [N, HID]

    gate_kernel<<<1, 32>>>(La, gW1, gb1, gW2, gb2);
    lut_kernel<<<dim3(TLUT/128, E_), 128>>>(eW1, eb1, eW2, eb2, eW3, eb3);
    vs_kernel<<<1024, 256>>>(U);
    gemmD_tc<<<dim3(CIN_/64, 2, NS2), 256>>>(U, X);     // launch #4 -> profiled
    reduceM_kernel<<<dim3(K_, 2), 256>>>();
    pgemm_tc<<<dim3(HID_/64, 4, PZ), 256>>>(Ww);
    gemmE_tc<<<dim3(N_/128, HID_/64), 256>>>(U, Wb, hidden);
    bn_partial<<<256, 256>>>(hidden);
    bn_final<<<1, HID_>>>(gamma, beta);
    final_kernel<<<N_/16, 256>>>(hidden, Mw, Mb, logits);
}

// round 13
// speedup vs baseline: 1.4965x; 1.4336x over previous
#include <cuda_runtime.h>
#include <cuda_bf16.h>
#include <math.h>

#define N_    8192
#define K_    200
#define CIN_  512
#define HID_  256
#define COUT_ 40
#define E_    5
#define MH_   64
#define KG_   40
#define TLUT  4096
#define NS2   32
#define PZ    8
#define EPS_  1e-5f

// ---------------- device scratch ----------------
__device__ __align__(16) float d_g[E_];
__device__ __align__(16) float d_lut[E_*TLUT];
__device__ __align__(16) float d_vpart[1024*K_];
__device__ __align__(16) float d_Mpart[(size_t)NS2*256*CIN_];
__device__ __align__(16) float d_M[256*CIN_];
__device__ __align__(16) float d_s[K_];
__device__ __align__(16) float d_Ppart[(size_t)PZ*256*HID_];
__device__ __align__(16) float d_P[K_*HID_];
__device__ __align__(16) float d_bnsum[256*HID_];
__device__ __align__(16) float d_bnsq[256*HID_];
__device__ __align__(16) float d_scale[HID_];
__device__ __align__(16) float d_shift[HID_];

// ---------------- helpers ----------------
__device__ __forceinline__ void split_tf32(float v, float& hi, float& lo){
    unsigned h; asm("cvt.rna.tf32.f32 %0, %1;" : "=r"(h) : "f"(v));
    float hf = __uint_as_float(h);
    float r = v - hf;
    unsigned l; asm("cvt.rna.tf32.f32 %0, %1;" : "=r"(l) : "f"(r));
    hi = hf; lo = __uint_as_float(l);
}
__device__ __forceinline__ void mma_tf32(float* d, const unsigned* a, const unsigned* b){
    asm volatile(
        "mma.sync.aligned.m16n8k8.row.col.f32.tf32.tf32.f32 "
        "{%0,%1,%2,%3},{%4,%5,%6,%7},{%8,%9},{%0,%1,%2,%3};"
        : "+f"(d[0]), "+f"(d[1]), "+f"(d[2]), "+f"(d[3])
        : "r"(a[0]), "r"(a[1]), "r"(a[2]), "r"(a[3]), "r"(b[0]), "r"(b[1]));
}
__device__ __forceinline__ void mma_bf16(float* d, const unsigned* a, const unsigned* b){
    asm volatile(
        "mma.sync.aligned.m16n8k16.row.col.f32.bf16.bf16.f32 "
        "{%0,%1,%2,%3},{%4,%5,%6,%7},{%8,%9},{%0,%1,%2,%3};"
        : "+f"(d[0]), "+f"(d[1]), "+f"(d[2]), "+f"(d[3])
        : "r"(a[0]), "r"(a[1]), "r"(a[2]), "r"(a[3]), "r"(b[0]), "r"(b[1]));
}
__device__ __forceinline__ void ldsm_x4(unsigned* r, unsigned addr){
    asm volatile("ldmatrix.sync.aligned.m8n8.x4.shared.b16 {%0,%1,%2,%3}, [%4];"
        : "=r"(r[0]), "=r"(r[1]), "=r"(r[2]), "=r"(r[3]) : "r"(addr));
}
__device__ __forceinline__ void ldsm_x4_t(unsigned* r, unsigned addr){
    asm volatile("ldmatrix.sync.aligned.m8n8.x4.trans.shared.b16 {%0,%1,%2,%3}, [%4];"
        : "=r"(r[0]), "=r"(r[1]), "=r"(r[2]), "=r"(r[3]) : "r"(addr));
}
__device__ __forceinline__ void split_bf(float v, float& h, float& l){
    float hf = __bfloat162float(__float2bfloat16_rn(v));
    h = hf; l = v - hf;
}
__device__ __forceinline__ unsigned pack2(float a, float b){
    __nv_bfloat162 t = __floats2bfloat162_rn(a, b);
    return *reinterpret_cast<unsigned*>(&t);
}

// ---------------- gate ----------------
__global__ void gate_kernel(const float* __restrict__ La, const float* __restrict__ gW1,
                            const float* __restrict__ gb1, const float* __restrict__ gW2,
                            const float* __restrict__ gb2){
    if (threadIdx.x != 0) return;
    float stats[E_];
    for (int e = 0; e < E_; e++){
        float s = 0.f;
        for (int i = 0; i < KG_; i++) s += La[e*KG_ + i];
        stats[e] = s / (float)KG_;
    }
    float t1[E_];
    for (int j = 0; j < E_; j++){
        float z = gb1[j];
        for (int i = 0; i < E_; i++) z += stats[i]*gW1[i*E_+j];
        t1[j] = fmaxf(z, 0.f);
    }
    float t2[E_]; float mx = -1e30f;
    for (int j = 0; j < E_; j++){
        float z = gb2[j];
        for (int i = 0; i < E_; i++) z += t1[i]*gW2[i*E_+j];
        t2[j] = z; mx = fmaxf(mx, z);
    }
    float den = 0.f;
    for (int j = 0; j < E_; j++){ t2[j] = expf(t2[j]-mx); den += t2[j]; }
    for (int j = 0; j < E_; j++) d_g[j] = t2[j]/den;
}

// ---------------- LUT build ----------------
__global__ __launch_bounds__(128) void lut_kernel(
        const float* __restrict__ eW1, const float* __restrict__ eb1,
        const float* __restrict__ eW2, const float* __restrict__ eb2,
        const float* __restrict__ eW3, const float* __restrict__ eb3){
    int e = blockIdx.y;
    __shared__ __align__(16) float w2t[MH_*MH_];
    __shared__ float w1[MH_], b1[MH_], b2s[MH_], w3[MH_];
    for (int i = threadIdx.x; i < MH_*MH_; i += blockDim.x){
        int h = i >> 6, g = i & 63;
        w2t[g*MH_ + h] = eW2[(e*MH_ + h)*MH_ + g];
    }
    if (threadIdx.x < MH_){
        int t = threadIdx.x;
        w1[t]  = eW1[e*MH_+t];
        b1[t]  = eb1[e*MH_+t];
        b2s[t] = eb2[e*MH_+t];
        w3[t]  = eW3[e*MH_+t];
    }
    __syncthreads();
    int j = blockIdx.x*blockDim.x + threadIdx.x;
    float u = -8.f + 16.f*(float)j/(float)(TLUT-1);
    float h1[MH_];
    #pragma unroll
    for (int h = 0; h < MH_; h++) h1[h] = fmaxf(fmaf(u, w1[h], b1[h]), 0.f);
    float acc = eb3[e];
    #pragma unroll 2
    for (int g = 0; g < MH_; g++){
        float z = b2s[g];
        const float4* row = (const float4*)(w2t + g*MH_);
        #pragma unroll
        for (int q = 0; q < 16; q++){
            float4 w = row[q];
            z = fmaf(h1[4*q+0], w.x, z);
            z = fmaf(h1[4*q+1], w.y, z);
            z = fmaf(h1[4*q+2], w.z, z);
            z = fmaf(h1[4*q+3], w.w, z);
        }
        acc = fmaf(fmaxf(z, 0.f), w3[g], acc);
    }
    d_lut[e*TLUT + j] = acc;
}

// ---------------- vs partials ----------------
__global__ __launch_bounds__(256) void vs_kernel(const float* __restrict__ U){
    int b = blockIdx.x;
    int col = threadIdx.x;
    if (col >= K_) return;
    int e = col / KG_;
    const float* lut = d_lut + e*TLUT;
    const float invd = (float)(TLUT-1)/16.f;
    float sum = 0.f;
    #pragma unroll
    for (int r = 0; r < 8; r++){
        float u = U[(size_t)(b*8+r)*K_ + col];
        float tt = (u + 8.f)*invd;
        int i = (int)floorf(tt);
        i = min(max(i, 0), TLUT-2);
        float fr = tt - (float)i;
        float a = __ldg(lut + i);
        float bb = __ldg(lut + i + 1);
        sum += a + (bb - a)*fr;
    }
    d_vpart[b*K_ + col] = sum;
}

// ---------------- gemmD: Mpart[z] = U[z]^T @ X[z]; bf16x3 + ldmatrix ----------------
// tile 128m x 64n; smem staged [k][m]/[k][n] (natural), ldmatrix.trans; 16 stages of k16
__global__ __launch_bounds__(256) void gemmD_tc(const float* __restrict__ U, const float* __restrict__ X){
    __shared__ __align__(16) unsigned short Ahs[2][16][136], Als[2][16][136];  // 272B rows
    __shared__ __align__(16) unsigned short Bhs[2][16][72],  Bls[2][16][72];   // 144B rows
    int n0 = blockIdx.x*64;
    int m0 = blockIdx.y*128;
    int rbase = blockIdx.z*256;
    int tid = threadIdx.x;
    int lane = tid & 31, warp = tid >> 5;
    int wm = warp & 3, wn = warp >> 2;          // 4x2 warps, warp tile 32m x 32n
    int g = lane >> 2, t = lane & 3;
    int lr = lane & 7, lg = lane >> 3;

    // loaders
    int akk = tid >> 5;            // rows akk, akk+8
    int ac4 = (tid & 31) * 4;
    bool aval = (m0 + ac4 < K_);
    int bkk = tid >> 4;            // 0..15
    int bc4 = (tid & 15) * 4;

    // fragment byte offsets within one buffer
    unsigned a_off[2], b_off[2];
    #pragma unroll
    for (int mf = 0; mf < 2; mf++){
        int m = wm*32 + mf*16 + (lg & 1)*8;
        int k = lr + (lg >> 1)*8;
        a_off[mf] = (unsigned)(k*272 + m*2);
    }
    #pragma unroll
    for (int nfp = 0; nfp < 2; nfp++){
        int k = lr + (lg & 1)*8;
        int n = wn*32 + nfp*16 + (lg >> 1)*8;
        b_off[nfp] = (unsigned)(k*144 + n*2);
    }
    unsigned ah_b[2] = { (unsigned)__cvta_generic_to_shared(&Ahs[0][0][0]),
                         (unsigned)__cvta_generic_to_shared(&Ahs[1][0][0]) };
    unsigned al_b[2] = { (unsigned)__cvta_generic_to_shared(&Als[0][0][0]),
                         (unsigned)__cvta_generic_to_shared(&Als[1][0][0]) };
    unsigned bh_b[2] = { (unsigned)__cvta_generic_to_shared(&Bhs[0][0][0]),
                         (unsigned)__cvta_generic_to_shared(&Bhs[1][0][0]) };
    unsigned bl_b[2] = { (unsigned)__cvta_generic_to_shared(&Bls[0][0][0]),
                         (unsigned)__cvta_generic_to_shared(&Bls[1][0][0]) };

    float acc[2][4][4];
    #pragma unroll
    for (int i = 0; i < 2; i++)
        #pragma unroll
        for (int j = 0; j < 4; j++){
            acc[i][j][0]=0.f; acc[i][j][1]=0.f; acc[i][j][2]=0.f; acc[i][j][3]=0.f;
        }

    float4 u0 = make_float4(0.f,0.f,0.f,0.f), u1 = u0, xv;
    auto LOAD = [&](int s){
        int row = rbase + s*16;
        if (aval){
            u0 = *(const float4*)(U + (size_t)(row+akk)*K_   + m0 + ac4);
            u1 = *(const float4*)(U + (size_t)(row+akk+8)*K_ + m0 + ac4);
        }
        xv = *(const float4*)(X + (size_t)(row+bkk)*CIN_ + n0 + bc4);
    };
    auto STORE = [&](int p){
        float h0,l0,h1,l1,h2,l2,h3,l3;
        split_bf(u0.x,h0,l0); split_bf(u0.y,h1,l1); split_bf(u0.z,h2,l2); split_bf(u0.w,h3,l3);
        *(uint2*)&Ahs[p][akk][ac4] = make_uint2(pack2(h0,h1), pack2(h2,h3));
        *(uint2*)&Als[p][akk][ac4] = make_uint2(pack2(l0,l1), pack2(l2,l3));
        split_bf(u1.x,h0,l0); split_bf(u1.y,h1,l1); split_bf(u1.z,h2,l2); split_bf(u1.w,h3,l3);
        *(uint2*)&Ahs[p][akk+8][ac4] = make_uint2(pack2(h0,h1), pack2(h2,h3));
        *(uint2*)&Als[p][akk+8][ac4] = make_uint2(pack2(l0,l1), pack2(l2,l3));
        split_bf(xv.x,h0,l0); split_bf(xv.y,h1,l1); split_bf(xv.z,h2,l2); split_bf(xv.w,h3,l3);
        *(uint2*)&Bhs[p][bkk][bc4] = make_uint2(pack2(h0,h1), pack2(h2,h3));
        *(uint2*)&Bls[p][bkk][bc4] = make_uint2(pack2(l0,l1), pack2(l2,l3));
    };

    LOAD(0); STORE(0);
    __syncthreads();

    for (int s = 0; s < 16; s++){
        int p = s & 1;
        if (s < 15) LOAD(s+1);

        unsigned ah[2][4], al[2][4], bh[2][4], bl[2][4];
        #pragma unroll
        for (int mf = 0; mf < 2; mf++){
            ldsm_x4_t(ah[mf], ah_b[p] + a_off[mf]);
            ldsm_x4_t(al[mf], al_b[p] + a_off[mf]);
        }
        #pragma unroll
        for (int nfp = 0; nfp < 2; nfp++){
            ldsm_x4_t(bh[nfp], bh_b[p] + b_off[nfp]);
            ldsm_x4_t(bl[nfp], bl_b[p] + b_off[nfp]);
        }
        #pragma unroll
        for (int nf = 0; nf < 4; nf++){
            const unsigned* bhp = &bh[nf>>1][(nf&1)*2];
            const unsigned* blp = &bl[nf>>1][(nf&1)*2];
            #pragma unroll
            for (int mf = 0; mf < 2; mf++){
                mma_bf16(acc[mf][nf], ah[mf], bhp);
                mma_bf16(acc[mf][nf], al[mf], bhp);
                mma_bf16(acc[mf][nf], ah[mf], blp);
            }
        }
        if (s < 15) STORE(p ^ 1);
        __syncthreads();
    }

    float* out = d_Mpart + (size_t)blockIdx.z*256*CIN_;
    #pragma unroll
    for (int mf = 0; mf < 2; mf++){
        #pragma unroll
        for (int nf = 0; nf < 4; nf++){
            int m = m0 + wm*32 + mf*16 + g;
            int n = n0 + wn*32 + nf*8 + 2*t;
            *(float2*)(out + (size_t)m*CIN_ + n)     = make_float2(acc[mf][nf][0], acc[mf][nf][1]);
            *(float2*)(out + (size_t)(m+8)*CIN_ + n) = make_float2(acc[mf][nf][2], acc[mf][nf][3]);
        }
    }
}

// ---------------- reduceM: d_M = sum_z Mpart, and d_s[k] ----------------
__global__ __launch_bounds__(256) void reduceM_kernel(){
    int k = blockIdx.x;
    int c = blockIdx.y*256 + threadIdx.x;
    float s = 0.f;
    #pragma unroll
    for (int b = 0; b < NS2; b++) s += d_Mpart[(size_t)b*256*CIN_ + (size_t)k*CIN_ + c];
    d_M[(size_t)k*CIN_ + c] = s;

    if (blockIdx.y == 0){
        __shared__ float red[256];
        float v = 0.f;
        #pragma unroll
        for (int q = 0; q < 4; q++) v += d_vpart[(size_t)(threadIdx.x + q*256)*K_ + k];
        red[threadIdx.x] = v;
        __syncthreads();
        for (int off = 128; off > 0; off >>= 1){
            if (threadIdx.x < off) red[threadIdx.x] += red[threadIdx.x + off];
            __syncthreads();
        }
        if (threadIdx.x == 0) d_s[k] = d_g[k/KG_] * (red[0] / (float)N_);
    }
}

// ---------------- pgemm split-K (tf32x3, unchanged) ----------------
#define PPAD 72
__global__ __launch_bounds__(256) void pgemm_tc(const float* __restrict__ Ww){
    __shared__ float Ah[2][8][PPAD], Al[2][8][PPAD], Bh[2][8][PPAD], Bl[2][8][PPAD];
    int n0 = blockIdx.x*64;
    int m0 = blockIdx.y*64;
    int z  = blockIdx.z;
    int tid = threadIdx.x;
    int lane = tid & 31, warp = tid >> 5;
    int wm = warp >> 2, wn = warp & 3;
    int g = lane >> 2, t = lane & 3;

    int arow = tid >> 1, aq = tid & 1;
    bool aval = (m0 + arow < K_);
    int bkk = (tid - 128) >> 4, bc4 = ((tid - 128) & 15) * 4;

    float acc[2][2][4];
    #pragma unroll
    for (int i = 0; i < 2; i++)
        #pragma unroll
        for (int j = 0; j < 2; j++){
            acc[i][j][0]=0.f; acc[i][j][1]=0.f; acc[i][j][2]=0.f; acc[i][j][3]=0.f;
        }

    float4 av, bv;
    auto LOAD = [&](int s){
        if (tid < 128)
            av = aval ? *(const float4*)(d_M + (size_t)(m0+arow)*CIN_ + z*64 + s*8 + aq*4)
                      : make_float4(0.f,0.f,0.f,0.f);
        else
            bv = *(const float4*)(Ww + (size_t)(z*64 + s*8 + bkk)*HID_ + n0 + bc4);
    };
    auto STORE = [&](int p){
        float h, l;
        if (tid < 128){
            split_tf32(av.x, h, l); Ah[p][aq*4+0][arow]=h; Al[p][aq*4+0][arow]=l;
            split_tf32(av.y, h, l); Ah[p][aq*4+1][arow]=h; Al[p][aq*4+1][arow]=l;
            split_tf32(av.z, h, l); Ah[p][aq*4+2][arow]=h; Al[p][aq*4+2][arow]=l;
            split_tf32(av.w, h, l); Ah[p][aq*4+3][arow]=h; Al[p][aq*4+3][arow]=l;
        } else {
            split_tf32(bv.x, h, l); Bh[p][bkk][bc4+0]=h; Bl[p][bkk][bc4+0]=l;
            split_tf32(bv.y, h, l); Bh[p][bkk][bc4+1]=h; Bl[p][bkk][bc4+1]=l;
            split_tf32(bv.z, h, l); Bh[p][bkk][bc4+2]=h; Bl[p][bkk][bc4+2]=l;
            split_tf32(bv.w, h, l); Bh[p][bkk][bc4+3]=h; Bl[p][bkk][bc4+3]=l;
        }
    };

    LOAD(0); STORE(0);
    __syncthreads();

    for (int s = 0; s < 8; s++){
        int p = s & 1;
        if (s < 7) LOAD(s+1);

        unsigned ah[2][4], al[2][4];
        #pragma unroll
        for (int mf = 0; mf < 2; mf++){
            int m = wm*32 + mf*16 + g;
            ah[mf][0] = __float_as_uint(Ah[p][t  ][m  ]);
            ah[mf][1] = __float_as_uint(Ah[p][t  ][m+8]);
            ah[mf][2] = __float_as_uint(Ah[p][t+4][m  ]);
            ah[mf][3] = __float_as_uint(Ah[p][t+4][m+8]);
            al[mf][0] = __float_as_uint(Al[p][t  ][m  ]);
            al[mf][1] = __float_as_uint(Al[p][t  ][m+8]);
            al[mf][2] = __float_as_uint(Al[p][t+4][m  ]);
            al[mf][3] = __float_as_uint(Al[p][t+4][m+8]);
        }
        #pragma unroll
        for (int nf = 0; nf < 2; nf++){
            int n = wn*16 + nf*8 + g;
            unsigned bh2[2] = { __float_as_uint(Bh[p][t][n]), __float_as_uint(Bh[p][t+4][n]) };
            unsigned bl2[2] = { __float_as_uint(Bl[p][t][n]), __float_as_uint(Bl[p][t+4][n]) };
            #pragma unroll
            for (int mf = 0; mf < 2; mf++){
                mma_tf32(acc[mf][nf], ah[mf], bh2);
                mma_tf32(acc[mf][nf], al[mf], bh2);
                mma_tf32(acc[mf][nf], ah[mf], bl2);
            }
        }
        if (s < 7) STORE(p ^ 1);
        __syncthreads();
    }

    float* out = d_Ppart + (size_t)z*256*HID_;
    #pragma unroll
    for (int mf = 0; mf < 2; mf++){
        #pragma unroll
        for (int nf = 0; nf < 2; nf++){
            int m = m0 + wm*32 + mf*16 + g;
            int n = n0 + wn*16 + nf*8 + 2*t;
            if (m < K_)
                *(float2*)(out + (size_t)m*HID_ + n) = make_float2(acc[mf][nf][0], acc[mf][nf][1]);
            if (m + 8 < K_)
                *(float2*)(out + (size_t)(m+8)*HID_ + n) = make_float2(acc[mf][nf][2], acc[mf][nf][3]);
        }
    }
}

// ---------------- reduceP: d_P[k,:] = s[k] * sum_z Ppart ----------------
__global__ __launch_bounds__(256) void reduceP_kernel(){
    int k = blockIdx.x;
    int n = threadIdx.x;
    float s = 0.f;
    #pragma unroll
    for (int z = 0; z < PZ; z++) s += d_Ppart[(size_t)z*256*HID_ + (size_t)k*HID_ + n];
    d_P[(size_t)k*HID_ + n] = s * d_s[k];
}

// ---------------- gemmE: hidden = U @ P + Wb; bf16x3 + ldmatrix ----------------
// tile 128m x 64n; A smem [m][k16] (natural), B smem [k][n]; 13 stages of k16 (200 -> pad 208)
__global__ __launch_bounds__(256) void gemmE_tc(const float* __restrict__ U, const float* __restrict__ Wb,
                                                float* __restrict__ hid){
    __shared__ __align__(16) unsigned short Ahs[2][128][24], Als[2][128][24];  // 48B rows
    __shared__ __align__(16) unsigned short Bhs[2][16][72],  Bls[2][16][72];   // 144B rows
    __shared__ float wbs[64];
    int m0 = blockIdx.x*128;
    int n0 = blockIdx.y*64;
    int tid = threadIdx.x;
    int lane = tid & 31, warp = tid >> 5;
    int wm = warp & 3, wn = warp >> 2;
    int g = lane >> 2, t = lane & 3;
    int lr = lane & 7, lg = lane >> 3;
    if (tid < 64) wbs[tid] = Wb[n0 + tid];

    int am = tid >> 1, akh = tid & 1;          // A loader: row am, k half akh
    int bkk = tid >> 4, bc4 = (tid & 15) * 4;  // B loader

    unsigned a_off[2], b_off[2];
    #pragma unroll
    for (int mf = 0; mf < 2; mf++){
        int row = wm*32 + mf*16 + lr + (lg & 1)*8;
        int k = (lg >> 1)*8;
        a_off[mf] = (unsigned)(row*48 + k*2);
    }
    #pragma unroll
    for (int nfp = 0; nfp < 2; nfp++){
        int k = lr + (lg & 1)*8;
        int n = wn*32 + nfp*16 + (lg >> 1)*8;
        b_off[nfp] = (unsigned)(k*144 + n*2);
    }
    unsigned ah_b[2] = { (unsigned)__cvta_generic_to_shared(&Ahs[0][0][0]),
                         (unsigned)__cvta_generic_to_shared(&Ahs[1][0][0]) };
    unsigned al_b[2] = { (unsigned)__cvta_generic_to_shared(&Als[0][0][0]),
                         (unsigned)__cvta_generic_to_shared(&Als[1][0][0]) };
    unsigned bh_b[2] = { (unsigned)__cvta_generic_to_shared(&Bhs[0][0][0]),
                         (unsigned)__cvta_generic_to_shared(&Bhs[1][0][0]) };
    unsigned bl_b[2] = { (unsigned)__cvta_generic_to_shared(&Bls[0][0][0]),
                         (unsigned)__cvta_generic_to_shared(&Bls[1][0][0]) };

    float acc[2][4][4];
    #pragma unroll
    for (int i = 0; i < 2; i++)
        #pragma unroll
        for (int j = 0; j < 4; j++){
            acc[i][j][0]=0.f; acc[i][j][1]=0.f; acc[i][j][2]=0.f; acc[i][j][3]=0.f;
        }

    float4 av0, av1, bv;
    auto LOAD = [&](int s){
        int k0 = s*16 + akh*8;
        if (k0 < K_){
            const float* pa = U + (size_t)(m0+am)*K_ + k0;
            av0 = *(const float4*)pa;
            av1 = *(const float4*)(pa + 4);
        } else {
            av0 = make_float4(0.f,0.f,0.f,0.f); av1 = av0;
        }
        int kb = s*16 + bkk;
        bv = (kb < K_) ? *(const float4*)(d_P + (size_t)kb*HID_ + n0 + bc4)
                       : make_float4(0.f,0.f,0.f,0.f);
    };
    auto STORE = [&](int p){
        float h0,l0,h1,l1,h2,l2,h3,l3,h4,l4,h5,l5,h6,l6,h7,l7;
        split_bf(av0.x,h0,l0); split_bf(av0.y,h1,l1); split_bf(av0.z,h2,l2); split_bf(av0.w,h3,l3);
        split_bf(av1.x,h4,l4); split_bf(av1.y,h5,l5); split_bf(av1.z,h6,l6); split_bf(av1.w,h7,l7);
        *(uint4*)&Ahs[p][am][akh*8] = make_uint4(pack2(h0,h1), pack2(h2,h3), pack2(h4,h5), pack2(h6,h7));
        *(uint4*)&Als[p][am][akh*8] = make_uint4(pack2(l0,l1), pack2(l2,l3), pack2(l4,l5), pack2(l6,l7));
        split_bf(bv.x,h0,l0); split_bf(bv.y,h1,l1); split_bf(bv.z,h2,l2); split_bf(bv.w,h3,l3);
        *(uint2*)&Bhs[p][bkk][bc4] = make_uint2(pack2(h0,h1), pack2(h2,h3));
        *(uint2*)&Bls[p][bkk][bc4] = make_uint2(pack2(l0,l1), pack2(l2,l3));
    };

    LOAD(0); STORE(0);
    __syncthreads();

    for (int s = 0; s < 13; s++){
        int p = s & 1;
        if (s < 12) LOAD(s+1);

        unsigned ah[2][4], al[2][4], bh[2][4], bl[2][4];
        #pragma unroll
        for (int mf = 0; mf < 2; mf++){
            ldsm_x4(ah[mf], ah_b[p] + a_off[mf]);
            ldsm_x4(al[mf], al_b[p] + a_off[mf]);
        }
        #pragma unroll
        for (int nfp = 0; nfp < 2; nfp++){
            ldsm_x4_t(bh[nfp], bh_b[p] + b_off[nfp]);
            ldsm_x4_t(bl[nfp], bl_b[p] + b_off[nfp]);
        }
        #pragma unroll
        for (int nf = 0; nf < 4; nf++){
            const unsigned* bhp = &bh[nf>>1][(nf&1)*2];
            const unsigned* blp = &bl[nf>>1][(nf&1)*2];
            #pragma unroll
            for (int mf = 0; mf < 2; mf++){
                mma_bf16(acc[mf][nf], ah[mf], bhp);
                mma_bf16(acc[mf][nf], al[mf], bhp);
                mma_bf16(acc[mf][nf], ah[mf], blp);
            }
        }
        if (s < 12) STORE(p ^ 1);
        __syncthreads();
    }

    #pragma unroll
    for (int mf = 0; mf < 2; mf++){
        #pragma unroll
        for (int nf = 0; nf < 4; nf++){
            int m = m0 + wm*32 + mf*16 + g;
            int nl = wn*32 + nf*8 + 2*t;
            float2 v0 = make_float2(acc[mf][nf][0] + wbs[nl], acc[mf][nf][1] + wbs[nl+1]);
            float2 v1 = make_float2(acc[mf][nf][2] + wbs[nl], acc[mf][nf][3] + wbs[nl+1]);
            *(float2*)(hid + (size_t)m*HID_ + n0 + nl)     = v0;
            *(float2*)(hid + (size_t)(m+8)*HID_ + n0 + nl) = v1;
        }
    }
}

// ---------------- BN stats ----------------
__global__ __launch_bounds__(256) void bn_partial(const float* __restrict__ hid){
    int j = threadIdx.x;
    int b = blockIdx.x;
    float sum = 0.f, sq = 0.f;
    #pragma unroll 4
    for (int r = 0; r < 32; r++){
        float v = hid[(size_t)(b*32+r)*HID_ + j];
        sum += v; sq = fmaf(v, v, sq);
    }
    d_bnsum[b*HID_ + j] = sum;
    d_bnsq [b*HID_ + j] = sq;
}

__global__ void bn_final(const float* __restrict__ gamma, const float* __restrict__ beta){
    int j = threadIdx.x;
    float sum = 0.f, sq = 0.f;
    for (int s = 0; s < 256; s++){ sum += d_bnsum[s*HID_+j]; sq += d_bnsq[s*HID_+j]; }
    float mu  = sum / (float)N_;
    float var = sq / (float)N_ - mu*mu;
    float sc  = gamma[j] * rsqrtf(var + EPS_);
    d_scale[j] = sc;
    d_shift[j] = beta[j] - mu*sc;
}

// ---------------- head: 16 rows per block ----------------
__global__ __launch_bounds__(256) void final_kernel(const float* __restrict__ hid,
                                                    const float* __restrict__ Mw,
                                                    const float* __restrict__ Mb,
                                                    float* __restrict__ logits_out){
    __shared__ float h[16*260];
    __shared__ float lg[16*COUT_];
    __shared__ float lz[16];
    int r0 = blockIdx.x * 16;
    int tid = threadIdx.x;
    #pragma unroll
    for (int r = 0; r < 16; r++){
        float v = hid[(size_t)(r0+r)*HID_ + tid];
        h[r*260 + tid] = fmaxf(fmaf(v, d_scale[tid], d_shift[tid]), 0.f);
    }
    __syncthreads();
    for (int base = 0; base < 16*COUT_; base += 256){
        int idx = base + tid;
        if (idx < 16*COUT_){
            int row = idx / COUT_;
            int o   = idx - row*COUT_;
            float a = Mb[o];
            #pragma unroll 4
            for (int c = 0; c < HID_; c++)
                a = fmaf(h[row*260 + c], Mw[c*COUT_ + o], a);
            lg[idx] = a;
        }
    }
    __syncthreads();
    if (tid < 16){
        float mx = -1e30f;
        for (int o = 0; o < COUT_; o++) mx = fmaxf(mx, lg[tid*COUT_+o]);
        float s = 0.f;
        for (int o = 0; o < COUT_; o++) s += expf(lg[tid*COUT_+o]-mx);
        lz[tid] = mx + logf(s);
    }
    __syncthreads();
    for (int base = 0; base < 16*COUT_; base += 256){
        int idx = base + tid;
        if (idx < 16*COUT_){
            int row = idx / COUT_;
            logits_out[(size_t)r0*COUT_ + idx] = lg[idx] - lz[row];
        }
    }
}

// ---------------- launch ----------------
extern "C" void kernel_launch(void* const* d_in, const int* in_sizes, int n_in,
                              void* d_out, int out_size){
    const float* X     = (const float*)d_in[0];
    const float* La    = (const float*)d_in[1];
    const float* U     = (const float*)d_in[2];
    const float* eW1   = (const float*)d_in[3];
    const float* eb1   = (const float*)d_in[4];
    const float* eW2   = (const float*)d_in[5];
    const float* eb2   = (const float*)d_in[6];
    const float* eW3   = (const float*)d_in[7];
    const float* eb3   = (const float*)d_in[8];
    const float* gW1   = (const float*)d_in[9];
    const float* gb1   = (const float*)d_in[10];
    const float* gW2   = (const float*)d_in[11];
    const float* gb2   = (const float*)d_in[12];
    const float* Ww    = (const float*)d_in[13];
    const float* Wb    = (const float*)d_in[14];
    const float* gamma = (const float*)d_in[15];
    const float* beta  = (const float*)d_in[16];
    const float* Mw    = (const float*)d_in[17];
    const float* Mb    = (const float*)d_in[18];

    float* outF   = (float*)d_out;
    float* logits = outF;                              // [N, COUT]
    float* hidden = outF + (size_t)N_*COUT_;           // [N, HID]

    gate_kernel<<<1, 32>>>(La, gW1, gb1, gW2, gb2);
    lut_kernel<<<dim3(TLUT/128, E_), 128>>>(eW1, eb1, eW2, eb2, eW3, eb3);
    vs_kernel<<<1024, 256>>>(U);
    gemmD_tc<<<dim3(CIN_/64, 2, NS2), 256>>>(U, X);     // launch #4 -> profiled
    reduceM_kernel<<<dim3(K_, 2), 256>>>();
    pgemm_tc<<<dim3(HID_/64, 4, PZ), 256>>>(Ww);
    reduceP_kernel<<<K_, 256>>>();
    gemmE_tc<<<dim3(N_/128, HID_/64), 256>>>(U, Wb, hidden);
    bn_partial<<<256, 256>>>(hidden);
    bn_final<<<1, HID_>>>(gamma, beta);
    final_kernel<<<N_/16, 256>>>(hidden, Mw, Mb, logits);
}

// round 15
// speedup vs baseline: 1.8038x; 1.2053x over previous
#include <cuda_runtime.h>
#include <cuda_bf16.h>
#include <math.h>

#define N_    8192
#define K_    200
#define CIN_  512
#define HID_  256
#define COUT_ 40
#define E_    5
#define MH_   64
#define KG_   40
#define TLUT  4096
#define NS2   32
#define PZ    8
#define EPS_  1e-5f

// ---------------- device scratch ----------------
__device__ __align__(16) float d_g[E_];
__device__ __align__(16) float d_lut[E_*TLUT];
__device__ __align__(16) float d_vpart[1024*K_];
__device__ __align__(16) float d_Mpart[(size_t)NS2*256*CIN_];
__device__ __align__(16) float d_M[256*CIN_];
__device__ __align__(16) float d_s[K_];
__device__ __align__(16) float d_Ppart[(size_t)PZ*256*HID_];
__device__ __align__(16) float d_P[K_*HID_];
__device__ __align__(16) float d_bnsum[64*HID_];
__device__ __align__(16) float d_bnsq[64*HID_];
__device__ __align__(16) float d_scale[HID_];
__device__ __align__(16) float d_shift[HID_];

// ---------------- helpers ----------------
__device__ __forceinline__ void split_tf32(float v, float& hi, float& lo){
    unsigned h; asm("cvt.rna.tf32.f32 %0, %1;" : "=r"(h) : "f"(v));
    float hf = __uint_as_float(h);
    float r = v - hf;
    unsigned l; asm("cvt.rna.tf32.f32 %0, %1;" : "=r"(l) : "f"(r));
    hi = hf; lo = __uint_as_float(l);
}
__device__ __forceinline__ void mma_tf32(float* d, const unsigned* a, const unsigned* b){
    asm volatile(
        "mma.sync.aligned.m16n8k8.row.col.f32.tf32.tf32.f32 "
        "{%0,%1,%2,%3},{%4,%5,%6,%7},{%8,%9},{%0,%1,%2,%3};"
        : "+f"(d[0]), "+f"(d[1]), "+f"(d[2]), "+f"(d[3])
        : "r"(a[0]), "r"(a[1]), "r"(a[2]), "r"(a[3]), "r"(b[0]), "r"(b[1]));
}
__device__ __forceinline__ void mma_bf16(float* d, const unsigned* a, const unsigned* b){
    asm volatile(
        "mma.sync.aligned.m16n8k16.row.col.f32.bf16.bf16.f32 "
        "{%0,%1,%2,%3},{%4,%5,%6,%7},{%8,%9},{%0,%1,%2,%3};"
        : "+f"(d[0]), "+f"(d[1]), "+f"(d[2]), "+f"(d[3])
        : "r"(a[0]), "r"(a[1]), "r"(a[2]), "r"(a[3]), "r"(b[0]), "r"(b[1]));
}
__device__ __forceinline__ void ldsm_x4(unsigned* r, unsigned addr){
    asm volatile("ldmatrix.sync.aligned.m8n8.x4.shared.b16 {%0,%1,%2,%3}, [%4];"
        : "=r"(r[0]), "=r"(r[1]), "=r"(r[2]), "=r"(r[3]) : "r"(addr));
}
__device__ __forceinline__ void ldsm_x4_t(unsigned* r, unsigned addr){
    asm volatile("ldmatrix.sync.aligned.m8n8.x4.trans.shared.b16 {%0,%1,%2,%3}, [%4];"
        : "=r"(r[0]), "=r"(r[1]), "=r"(r[2]), "=r"(r[3]) : "r"(addr));
}
__device__ __forceinline__ void split_bf(float v, float& h, float& l){
    float hf = __bfloat162float(__float2bfloat16_rn(v));
    h = hf; l = v - hf;
}
__device__ __forceinline__ unsigned pack2(float a, float b){
    __nv_bfloat162 t = __floats2bfloat162_rn(a, b);
    return *reinterpret_cast<unsigned*>(&t);
}

// ---------------- LUT build + gate (fused) ----------------
__global__ __launch_bounds__(128) void lutgate_kernel(
        const float* __restrict__ eW1, const float* __restrict__ eb1,
        const float* __restrict__ eW2, const float* __restrict__ eb2,
        const float* __restrict__ eW3, const float* __restrict__ eb3,
        const float* __restrict__ La,  const float* __restrict__ gW1,
        const float* __restrict__ gb1, const float* __restrict__ gW2,
        const float* __restrict__ gb2){
    int e = blockIdx.y;
    __shared__ __align__(16) float w2t[MH_*MH_];
    __shared__ float w1[MH_], b1[MH_], b2s[MH_], w3[MH_];
    for (int i = threadIdx.x; i < MH_*MH_; i += blockDim.x){
        int h = i >> 6, g = i & 63;
        w2t[g*MH_ + h] = eW2[(e*MH_ + h)*MH_ + g];
    }
    if (threadIdx.x < MH_){
        int t = threadIdx.x;
        w1[t]  = eW1[e*MH_+t];
        b1[t]  = eb1[e*MH_+t];
        b2s[t] = eb2[e*MH_+t];
        w3[t]  = eW3[e*MH_+t];
    }
    __syncthreads();
    int j = blockIdx.x*blockDim.x + threadIdx.x;
    float u = -8.f + 16.f*(float)j/(float)(TLUT-1);
    float h1[MH_];
    #pragma unroll
    for (int h = 0; h < MH_; h++) h1[h] = fmaxf(fmaf(u, w1[h], b1[h]), 0.f);
    float acc = eb3[e];
    #pragma unroll 2
    for (int g = 0; g < MH_; g++){
        float z = b2s[g];
        const float4* row = (const float4*)(w2t + g*MH_);
        #pragma unroll
        for (int q = 0; q < 16; q++){
            float4 w = row[q];
            z = fmaf(h1[4*q+0], w.x, z);
            z = fmaf(h1[4*q+1], w.y, z);
            z = fmaf(h1[4*q+2], w.z, z);
            z = fmaf(h1[4*q+3], w.w, z);
        }
        acc = fmaf(fmaxf(z, 0.f), w3[g], acc);
    }
    d_lut[e*TLUT + j] = acc;

    if (blockIdx.x == 0 && blockIdx.y == 0 && threadIdx.x == 0){
        float stats[E_];
        for (int ee = 0; ee < E_; ee++){
            float s = 0.f;
            for (int i = 0; i < KG_; i++) s += La[ee*KG_ + i];
            stats[ee] = s / (float)KG_;
        }
        float t1[E_];
        for (int jj = 0; jj < E_; jj++){
            float z = gb1[jj];
            for (int i = 0; i < E_; i++) z += stats[i]*gW1[i*E_+jj];
            t1[jj] = fmaxf(z, 0.f);
        }
        float t2[E_]; float mx = -1e30f;
        for (int jj = 0; jj < E_; jj++){
            float z = gb2[jj];
            for (int i = 0; i < E_; i++) z += t1[i]*gW2[i*E_+jj];
            t2[jj] = z; mx = fmaxf(mx, z);
        }
        float den = 0.f;
        for (int jj = 0; jj < E_; jj++){ t2[jj] = expf(t2[jj]-mx); den += t2[jj]; }
        for (int jj = 0; jj < E_; jj++) d_g[jj] = t2[jj]/den;
    }
}

// ---------------- vs partials ----------------
__global__ __launch_bounds__(256) void vs_kernel(const float* __restrict__ U){
    int b = blockIdx.x;
    int col = threadIdx.x;
    if (col >= K_) return;
    int e = col / KG_;
    const float* lut = d_lut + e*TLUT;
    const float invd = (float)(TLUT-1)/16.f;
    float sum = 0.f;
    #pragma unroll
    for (int r = 0; r < 8; r++){
        float u = U[(size_t)(b*8+r)*K_ + col];
        float tt = (u + 8.f)*invd;
        int i = (int)floorf(tt);
        i = min(max(i, 0), TLUT-2);
        float fr = tt - (float)i;
        float a = __ldg(lut + i);
        float bb = __ldg(lut + i + 1);
        sum += a + (bb - a)*fr;
    }
    d_vpart[b*K_ + col] = sum;
}

// ---------------- gemmD: Mpart[z] = U[z]^T @ X[z]; bf16x3 + ldmatrix ----------------
__global__ __launch_bounds__(256) void gemmD_tc(const float* __restrict__ U, const float* __restrict__ X){
    __shared__ __align__(16) unsigned short Ahs[2][16][136], Als[2][16][136];
    __shared__ __align__(16) unsigned short Bhs[2][16][72],  Bls[2][16][72];
    int n0 = blockIdx.x*64;
    int m0 = blockIdx.y*128;
    int rbase = blockIdx.z*256;
    int tid = threadIdx.x;
    int lane = tid & 31, warp = tid >> 5;
    int wm = warp & 3, wn = warp >> 2;
    int g = lane >> 2, t = lane & 3;
    int lr = lane & 7, lg = lane >> 3;

    int akk = tid >> 5;
    int ac4 = (tid & 31) * 4;
    bool aval = (m0 + ac4 < K_);
    int bkk = tid >> 4;
    int bc4 = (tid & 15) * 4;

    unsigned a_off[2], b_off[2];
    #pragma unroll
    for (int mf = 0; mf < 2; mf++){
        int m = wm*32 + mf*16 + (lg & 1)*8;
        int k = lr + (lg >> 1)*8;
        a_off[mf] = (unsigned)(k*272 + m*2);
    }
    #pragma unroll
    for (int nfp = 0; nfp < 2; nfp++){
        int k = lr + (lg & 1)*8;
        int n = wn*32 + nfp*16 + (lg >> 1)*8;
        b_off[nfp] = (unsigned)(k*144 + n*2);
    }
    unsigned ah_b[2] = { (unsigned)__cvta_generic_to_shared(&Ahs[0][0][0]),
                         (unsigned)__cvta_generic_to_shared(&Ahs[1][0][0]) };
    unsigned al_b[2] = { (unsigned)__cvta_generic_to_shared(&Als[0][0][0]),
                         (unsigned)__cvta_generic_to_shared(&Als[1][0][0]) };
    unsigned bh_b[2] = { (unsigned)__cvta_generic_to_shared(&Bhs[0][0][0]),
                         (unsigned)__cvta_generic_to_shared(&Bhs[1][0][0]) };
    unsigned bl_b[2] = { (unsigned)__cvta_generic_to_shared(&Bls[0][0][0]),
                         (unsigned)__cvta_generic_to_shared(&Bls[1][0][0]) };

    float acc[2][4][4];
    #pragma unroll
    for (int i = 0; i < 2; i++)
        #pragma unroll
        for (int j = 0; j < 4; j++){
            acc[i][j][0]=0.f; acc[i][j][1]=0.f; acc[i][j][2]=0.f; acc[i][j][3]=0.f;
        }

    float4 u0 = make_float4(0.f,0.f,0.f,0.f), u1 = u0, xv;
    auto LOAD = [&](int s){
        int row = rbase + s*16;
        if (aval){
            u0 = *(const float4*)(U + (size_t)(row+akk)*K_   + m0 + ac4);
            u1 = *(const float4*)(U + (size_t)(row+akk+8)*K_ + m0 + ac4);
        }
        xv = *(const float4*)(X + (size_t)(row+bkk)*CIN_ + n0 + bc4);
    };
    auto STORE = [&](int p){
        float h0,l0,h1,l1,h2,l2,h3,l3;
        split_bf(u0.x,h0,l0); split_bf(u0.y,h1,l1); split_bf(u0.z,h2,l2); split_bf(u0.w,h3,l3);
        *(uint2*)&Ahs[p][akk][ac4] = make_uint2(pack2(h0,h1), pack2(h2,h3));
        *(uint2*)&Als[p][akk][ac4] = make_uint2(pack2(l0,l1), pack2(l2,l3));
        split_bf(u1.x,h0,l0); split_bf(u1.y,h1,l1); split_bf(u1.z,h2,l2); split_bf(u1.w,h3,l3);
        *(uint2*)&Ahs[p][akk+8][ac4] = make_uint2(pack2(h0,h1), pack2(h2,h3));
        *(uint2*)&Als[p][akk+8][ac4] = make_uint2(pack2(l0,l1), pack2(l2,l3));
        split_bf(xv.x,h0,l0); split_bf(xv.y,h1,l1); split_bf(xv.z,h2,l2); split_bf(xv.w,h3,l3);
        *(uint2*)&Bhs[p][bkk][bc4] = make_uint2(pack2(h0,h1), pack2(h2,h3));
        *(uint2*)&Bls[p][bkk][bc4] = make_uint2(pack2(l0,l1), pack2(l2,l3));
    };

    LOAD(0); STORE(0);
    __syncthreads();

    for (int s = 0; s < 16; s++){
        int p = s & 1;
        if (s < 15) LOAD(s+1);

        unsigned ah[2][4], al[2][4], bh[2][4], bl[2][4];
        #pragma unroll
        for (int mf = 0; mf < 2; mf++){
            ldsm_x4_t(ah[mf], ah_b[p] + a_off[mf]);
            ldsm_x4_t(al[mf], al_b[p] + a_off[mf]);
        }
        #pragma unroll
        for (int nfp = 0; nfp < 2; nfp++){
            ldsm_x4_t(bh[nfp], bh_b[p] + b_off[nfp]);
            ldsm_x4_t(bl[nfp], bl_b[p] + b_off[nfp]);
        }
        #pragma unroll
        for (int nf = 0; nf < 4; nf++){
            const unsigned* bhp = &bh[nf>>1][(nf&1)*2];
            const unsigned* blp = &bl[nf>>1][(nf&1)*2];
            #pragma unroll
            for (int mf = 0; mf < 2; mf++){
                mma_bf16(acc[mf][nf], ah[mf], bhp);
                mma_bf16(acc[mf][nf], al[mf], bhp);
                mma_bf16(acc[mf][nf], ah[mf], blp);
            }
        }
        if (s < 15) STORE(p ^ 1);
        __syncthreads();
    }

    float* out = d_Mpart + (size_t)blockIdx.z*256*CIN_;
    #pragma unroll
    for (int mf = 0; mf < 2; mf++){
        #pragma unroll
        for (int nf = 0; nf < 4; nf++){
            int m = m0 + wm*32 + mf*16 + g;
            int n = n0 + wn*32 + nf*8 + 2*t;
            *(float2*)(out + (size_t)m*CIN_ + n)     = make_float2(acc[mf][nf][0], acc[mf][nf][1]);
            *(float2*)(out + (size_t)(m+8)*CIN_ + n) = make_float2(acc[mf][nf][2], acc[mf][nf][3]);
        }
    }
}

// ---------------- reduceM: d_M = sum_z Mpart, and d_s[k] ----------------
__global__ __launch_bounds__(256) void reduceM_kernel(){
    int k = blockIdx.x;
    int c = blockIdx.y*256 + threadIdx.x;
    float s = 0.f;
    #pragma unroll
    for (int b = 0; b < NS2; b++) s += d_Mpart[(size_t)b*256*CIN_ + (size_t)k*CIN_ + c];
    d_M[(size_t)k*CIN_ + c] = s;

    if (blockIdx.y == 0){
        __shared__ float red[256];
        float v = 0.f;
        #pragma unroll
        for (int q = 0; q < 4; q++) v += d_vpart[(size_t)(threadIdx.x + q*256)*K_ + k];
        red[threadIdx.x] = v;
        __syncthreads();
        for (int off = 128; off > 0; off >>= 1){
            if (threadIdx.x < off) red[threadIdx.x] += red[threadIdx.x + off];
            __syncthreads();
        }
        if (threadIdx.x == 0) d_s[k] = d_g[k/KG_] * (red[0] / (float)N_);
    }
}

// ---------------- pgemm split-K (tf32x3) ----------------
#define PPAD 72
__global__ __launch_bounds__(256) void pgemm_tc(const float* __restrict__ Ww){
    __shared__ float Ah[2][8][PPAD], Al[2][8][PPAD], Bh[2][8][PPAD], Bl[2][8][PPAD];
    int n0 = blockIdx.x*64;
    int m0 = blockIdx.y*64;
    int z  = blockIdx.z;
    int tid = threadIdx.x;
    int lane = tid & 31, warp = tid >> 5;
    int wm = warp >> 2, wn = warp & 3;
    int g = lane >> 2, t = lane & 3;

    int arow = tid >> 1, aq = tid & 1;
    bool aval = (m0 + arow < K_);
    int bkk = (tid - 128) >> 4, bc4 = ((tid - 128) & 15) * 4;

    float acc[2][2][4];
    #pragma unroll
    for (int i = 0; i < 2; i++)
        #pragma unroll
        for (int j = 0; j < 2; j++){
            acc[i][j][0]=0.f; acc[i][j][1]=0.f; acc[i][j][2]=0.f; acc[i][j][3]=0.f;
        }

    float4 av, bv;
    auto LOAD = [&](int s){
        if (tid < 128)
            av = aval ? *(const float4*)(d_M + (size_t)(m0+arow)*CIN_ + z*64 + s*8 + aq*4)
                      : make_float4(0.f,0.f,0.f,0.f);
        else
            bv = *(const float4*)(Ww + (size_t)(z*64 + s*8 + bkk)*HID_ + n0 + bc4);
    };
    auto STORE = [&](int p){
        float h, l;
        if (tid < 128){
            split_tf32(av.x, h, l); Ah[p][aq*4+0][arow]=h; Al[p][aq*4+0][arow]=l;
            split_tf32(av.y, h, l); Ah[p][aq*4+1][arow]=h; Al[p][aq*4+1][arow]=l;
            split_tf32(av.z, h, l); Ah[p][aq*4+2][arow]=h; Al[p][aq*4+2][arow]=l;
            split_tf32(av.w, h, l); Ah[p][aq*4+3][arow]=h; Al[p][aq*4+3][arow]=l;
        } else {
            split_tf32(bv.x, h, l); Bh[p][bkk][bc4+0]=h; Bl[p][bkk][bc4+0]=l;
            split_tf32(bv.y, h, l); Bh[p][bkk][bc4+1]=h; Bl[p][bkk][bc4+1]=l;
            split_tf32(bv.z, h, l); Bh[p][bkk][bc4+2]=h; Bl[p][bkk][bc4+2]=l;
            split_tf32(bv.w, h, l); Bh[p][bkk][bc4+3]=h; Bl[p][bkk][bc4+3]=l;
        }
    };

    LOAD(0); STORE(0);
    __syncthreads();

    for (int s = 0; s < 8; s++){
        int p = s & 1;
        if (s < 7) LOAD(s+1);

        unsigned ah[2][4], al[2][4];
        #pragma unroll
        for (int mf = 0; mf < 2; mf++){
            int m = wm*32 + mf*16 + g;
            ah[mf][0] = __float_as_uint(Ah[p][t  ][m  ]);
            ah[mf][1] = __float_as_uint(Ah[p][t  ][m+8]);
            ah[mf][2] = __float_as_uint(Ah[p][t+4][m  ]);
            ah[mf][3] = __float_as_uint(Ah[p][t+4][m+8]);
            al[mf][0] = __float_as_uint(Al[p][t  ][m  ]);
            al[mf][1] = __float_as_uint(Al[p][t  ][m+8]);
            al[mf][2] = __float_as_uint(Al[p][t+4][m  ]);
            al[mf][3] = __float_as_uint(Al[p][t+4][m+8]);
        }
        #pragma unroll
        for (int nf = 0; nf < 2; nf++){
            int n = wn*16 + nf*8 + g;
            unsigned bh2[2] = { __float_as_uint(Bh[p][t][n]), __float_as_uint(Bh[p][t+4][n]) };
            unsigned bl2[2] = { __float_as_uint(Bl[p][t][n]), __float_as_uint(Bl[p][t+4][n]) };
            #pragma unroll
            for (int mf = 0; mf < 2; mf++){
                mma_tf32(acc[mf][nf], ah[mf], bh2);
                mma_tf32(acc[mf][nf], al[mf], bh2);
                mma_tf32(acc[mf][nf], ah[mf], bl2);
            }
        }
        if (s < 7) STORE(p ^ 1);
        __syncthreads();
    }

    float* out = d_Ppart + (size_t)z*256*HID_;
    #pragma unroll
    for (int mf = 0; mf < 2; mf++){
        #pragma unroll
        for (int nf = 0; nf < 2; nf++){
            int m = m0 + wm*32 + mf*16 + g;
            int n = n0 + wn*16 + nf*8 + 2*t;
            if (m < K_)
                *(float2*)(out + (size_t)m*HID_ + n) = make_float2(acc[mf][nf][0], acc[mf][nf][1]);
            if (m + 8 < K_)
                *(float2*)(out + (size_t)(m+8)*HID_ + n) = make_float2(acc[mf][nf][2], acc[mf][nf][3]);
        }
    }
}

// ---------------- reduceP ----------------
__global__ __launch_bounds__(256) void reduceP_kernel(){
    int k = blockIdx.x;
    int n = threadIdx.x;
    float s = 0.f;
    #pragma unroll
    for (int z = 0; z < PZ; z++) s += d_Ppart[(size_t)z*256*HID_ + (size_t)k*HID_ + n];
    d_P[(size_t)k*HID_ + n] = s * d_s[k];
}

// ---------------- gemmE: hidden = U @ P + Wb; bf16x3 + ldmatrix; fused BN partials ----------------
__global__ __launch_bounds__(256) void gemmE_tc(const float* __restrict__ U, const float* __restrict__ Wb,
                                                float* __restrict__ hid){
    __shared__ __align__(16) unsigned short Ahs[2][128][24], Als[2][128][24];
    __shared__ __align__(16) unsigned short Bhs[2][16][72],  Bls[2][16][72];
    __shared__ float wbs[64];
    __shared__ float bns[4][64], bnq[4][64];
    int m0 = blockIdx.x*128;
    int n0 = blockIdx.y*64;
    int tid = threadIdx.x;
    int lane = tid & 31, warp = tid >> 5;
    int wm = warp & 3, wn = warp >> 2;
    int g = lane >> 2, t = lane & 3;
    int lr = lane & 7, lg = lane >> 3;
    if (tid < 64) wbs[tid] = Wb[n0 + tid];

    int am = tid >> 1, akh = tid & 1;
    int bkk = tid >> 4, bc4 = (tid & 15) * 4;

    unsigned a_off[2], b_off[2];
    #pragma unroll
    for (int mf = 0; mf < 2; mf++){
        int row = wm*32 + mf*16 + lr + (lg & 1)*8;
        int k = (lg >> 1)*8;
        a_off[mf] = (unsigned)(row*48 + k*2);
    }
    #pragma unroll
    for (int nfp = 0; nfp < 2; nfp++){
        int k = lr + (lg & 1)*8;
        int n = wn*32 + nfp*16 + (lg >> 1)*8;
        b_off[nfp] = (unsigned)(k*144 + n*2);
    }
    unsigned ah_b[2] = { (unsigned)__cvta_generic_to_shared(&Ahs[0][0][0]),
                         (unsigned)__cvta_generic_to_shared(&Ahs[1][0][0]) };
    unsigned al_b[2] = { (unsigned)__cvta_generic_to_shared(&Als[0][0][0]),
                         (unsigned)__cvta_generic_to_shared(&Als[1][0][0]) };
    unsigned bh_b[2] = { (unsigned)__cvta_generic_to_shared(&Bhs[0][0][0]),
                         (unsigned)__cvta_generic_to_shared(&Bhs[1][0][0]) };
    unsigned bl_b[2] = { (unsigned)__cvta_generic_to_shared(&Bls[0][0][0]),
                         (unsigned)__cvta_generic_to_shared(&Bls[1][0][0]) };

    float acc[2][4][4];
    #pragma unroll
    for (int i = 0; i < 2; i++)
        #pragma unroll
        for (int j = 0; j < 4; j++){
            acc[i][j][0]=0.f; acc[i][j][1]=0.f; acc[i][j][2]=0.f; acc[i][j][3]=0.f;
        }

    float4 av0, av1, bv;
    auto LOAD = [&](int s){
        int k0 = s*16 + akh*8;
        if (k0 < K_){
            const float* pa = U + (size_t)(m0+am)*K_ + k0;
            av0 = *(const float4*)pa;
            av1 = *(const float4*)(pa + 4);
        } else {
            av0 = make_float4(0.f,0.f,0.f,0.f); av1 = av0;
        }
        int kb = s*16 + bkk;
        bv = (kb < K_) ? *(const float4*)(d_P + (size_t)kb*HID_ + n0 + bc4)
                       : make_float4(0.f,0.f,0.f,0.f);
    };
    auto STORE = [&](int p){
        float h0,l0,h1,l1,h2,l2,h3,l3,h4,l4,h5,l5,h6,l6,h7,l7;
        split_bf(av0.x,h0,l0); split_bf(av0.y,h1,l1); split_bf(av0.z,h2,l2); split_bf(av0.w,h3,l3);
        split_bf(av1.x,h4,l4); split_bf(av1.y,h5,l5); split_bf(av1.z,h6,l6); split_bf(av1.w,h7,l7);
        *(uint4*)&Ahs[p][am][akh*8] = make_uint4(pack2(h0,h1), pack2(h2,h3), pack2(h4,h5), pack2(h6,h7));
        *(uint4*)&Als[p][am][akh*8] = make_uint4(pack2(l0,l1), pack2(l2,l3), pack2(l4,l5), pack2(l6,l7));
        split_bf(bv.x,h0,l0); split_bf(bv.y,h1,l1); split_bf(bv.z,h2,l2); split_bf(bv.w,h3,l3);
        *(uint2*)&Bhs[p][bkk][bc4] = make_uint2(pack2(h0,h1), pack2(h2,h3));
        *(uint2*)&Bls[p][bkk][bc4] = make_uint2(pack2(l0,l1), pack2(l2,l3));
    };

    LOAD(0); STORE(0);
    __syncthreads();

    for (int s = 0; s < 13; s++){
        int p = s & 1;
        if (s < 12) LOAD(s+1);

        unsigned ah[2][4], al[2][4], bh[2][4], bl[2][4];
        #pragma unroll
        for (int mf = 0; mf < 2; mf++){
            ldsm_x4(ah[mf], ah_b[p] + a_off[mf]);
            ldsm_x4(al[mf], al_b[p] + a_off[mf]);
        }
        #pragma unroll
        for (int nfp = 0; nfp < 2; nfp++){
            ldsm_x4_t(bh[nfp], bh_b[p] + b_off[nfp]);
            ldsm_x4_t(bl[nfp], bl_b[p] + b_off[nfp]);
        }
        #pragma unroll
        for (int nf = 0; nf < 4; nf++){
            const unsigned* bhp = &bh[nf>>1][(nf&1)*2];
            const unsigned* blp = &bl[nf>>1][(nf&1)*2];
            #pragma unroll
            for (int mf = 0; mf < 2; mf++){
                mma_bf16(acc[mf][nf], ah[mf], bhp);
                mma_bf16(acc[mf][nf], al[mf], bhp);
                mma_bf16(acc[mf][nf], ah[mf], blp);
            }
        }
        if (s < 12) STORE(p ^ 1);
        __syncthreads();
    }

    // add bias, store hidden
    #pragma unroll
    for (int mf = 0; mf < 2; mf++){
        #pragma unroll
        for (int nf = 0; nf < 4; nf++){
            int nl = wn*32 + nf*8 + 2*t;
            acc[mf][nf][0] += wbs[nl];   acc[mf][nf][1] += wbs[nl+1];
            acc[mf][nf][2] += wbs[nl];   acc[mf][nf][3] += wbs[nl+1];
            int m = m0 + wm*32 + mf*16 + g;
            *(float2*)(hid + (size_t)m*HID_ + n0 + nl)     = make_float2(acc[mf][nf][0], acc[mf][nf][1]);
            *(float2*)(hid + (size_t)(m+8)*HID_ + n0 + nl) = make_float2(acc[mf][nf][2], acc[mf][nf][3]);
        }
    }
    // fused BN partial stats: per-column sums over this block's 128 rows
    #pragma unroll
    for (int nf = 0; nf < 4; nf++){
        #pragma unroll
        for (int b = 0; b < 2; b++){
            float v0 = acc[0][nf][b],   v1 = acc[0][nf][b+2];
            float v2 = acc[1][nf][b],   v3 = acc[1][nf][b+2];
            float ss = v0+v1+v2+v3;
            float sq = v0*v0+v1*v1+v2*v2+v3*v3;
            #pragma unroll
            for (int o = 4; o < 32; o <<= 1){
                ss += __shfl_xor_sync(0xffffffffu, ss, o);
                sq += __shfl_xor_sync(0xffffffffu, sq, o);
            }
            if (lane < 4){
                int col = wn*32 + nf*8 + 2*lane + b;
                bns[wm][col] = ss;
                bnq[wm][col] = sq;
            }
        }
    }
    __syncthreads();
    if (tid < 128){
        int col = tid & 63;
        if (tid < 64){
            float s = bns[0][col]+bns[1][col]+bns[2][col]+bns[3][col];
            d_bnsum[(size_t)blockIdx.x*HID_ + n0 + col] = s;
        } else {
            float s = bnq[0][col]+bnq[1][col]+bnq[2][col]+bnq[3][col];
            d_bnsq[(size_t)blockIdx.x*HID_ + n0 + col] = s;
        }
    }
}

// ---------------- BN final ----------------
__global__ void bn_final(const float* __restrict__ gamma, const float* __restrict__ beta){
    int j = threadIdx.x;
    float sum = 0.f, sq = 0.f;
    for (int s = 0; s < 64; s++){ sum += d_bnsum[s*HID_+j]; sq += d_bnsq[s*HID_+j]; }
    float mu  = sum / (float)N_;
    float var = sq / (float)N_ - mu*mu;
    float sc  = gamma[j] * rsqrtf(var + EPS_);
    d_scale[j] = sc;
    d_shift[j] = beta[j] - mu*sc;
}

// ---------------- head: logits = log_softmax(relu(BN(hidden)) @ Mw + Mb); bf16x3 TC ----------------
__global__ __launch_bounds__(256) void head_tc(const float* __restrict__ hid,
                                               const float* __restrict__ Mw,
                                               const float* __restrict__ Mb,
                                               float* __restrict__ out){
    __shared__ __align__(16) char pool[35840];
    unsigned short* Ahs = (unsigned short*)pool;            // [2][128][24]
    unsigned short* Als = (unsigned short*)(pool + 12288);
    unsigned short* Bhs = (unsigned short*)(pool + 24576);  // [2][16][72]
    unsigned short* Bls = (unsigned short*)(pool + 29184);
    float* scl = (float*)(pool + 33792);
    float* shf = (float*)(pool + 34816);
    float* lgs = (float*)pool;                              // [128][48] (aliases A bufs)
    float* lgz = (float*)(pool + 24576);                    // [128]     (aliases B bufs)

    int m0 = blockIdx.x*128;
    int tid = threadIdx.x;
    int lane = tid & 31, warp = tid >> 5;
    int wm = warp & 3, wn = warp >> 2;
    int g = lane >> 2, t = lane & 3;
    int lr = lane & 7, lg = lane >> 3;

    scl[tid] = d_scale[tid];
    shf[tid] = d_shift[tid];
    __syncthreads();

    int am = tid >> 1, akh = tid & 1;
    int bkk = tid >> 4, bc4 = (tid & 15)*4;

    unsigned a_off[2], b_off[2];
    #pragma unroll
    for (int mf = 0; mf < 2; mf++){
        int row = wm*32 + mf*16 + lr + (lg & 1)*8;
        int k = (lg >> 1)*8;
        a_off[mf] = (unsigned)(row*48 + k*2);
    }
    #pragma unroll
    for (int nfp = 0; nfp < 2; nfp++){
        int k = lr + (lg & 1)*8;
        int n = wn*32 + nfp*16 + (lg >> 1)*8;
        b_off[nfp] = (unsigned)(k*144 + n*2);
    }
    unsigned ah_b[2] = { (unsigned)__cvta_generic_to_shared(Ahs),
                         (unsigned)__cvta_generic_to_shared(Ahs) + 6144u };
    unsigned al_b[2] = { (unsigned)__cvta_generic_to_shared(Als),
                         (unsigned)__cvta_generic_to_shared(Als) + 6144u };
    unsigned bh_b[2] = { (unsigned)__cvta_generic_to_shared(Bhs),
                         (unsigned)__cvta_generic_to_shared(Bhs) + 2304u };
    unsigned bl_b[2] = { (unsigned)__cvta_generic_to_shared(Bls),
                         (unsigned)__cvta_generic_to_shared(Bls) + 2304u };

    float acc[2][4][4];
    #pragma unroll
    for (int i = 0; i < 2; i++)
        #pragma unroll
        for (int j = 0; j < 4; j++){
            acc[i][j][0]=0.f; acc[i][j][1]=0.f; acc[i][j][2]=0.f; acc[i][j][3]=0.f;
        }

    float hv[8]; float bb[4];
    auto LOAD = [&](int s){
        int k0 = s*16 + akh*8;
        const float* pa = hid + (size_t)(m0+am)*HID_ + k0;
        float4 v0 = *(const float4*)pa;
        float4 v1 = *(const float4*)(pa + 4);
        hv[0] = fmaxf(fmaf(v0.x, scl[k0+0], shf[k0+0]), 0.f);
        hv[1] = fmaxf(fmaf(v0.y, scl[k0+1], shf[k0+1]), 0.f);
        hv[2] = fmaxf(fmaf(v0.z, scl[k0+2], shf[k0+2]), 0.f);
        hv[3] = fmaxf(fmaf(v0.w, scl[k0+3], shf[k0+3]), 0.f);
        hv[4] = fmaxf(fmaf(v1.x, scl[k0+4], shf[k0+4]), 0.f);
        hv[5] = fmaxf(fmaf(v1.y, scl[k0+5], shf[k0+5]), 0.f);
        hv[6] = fmaxf(fmaf(v1.z, scl[k0+6], shf[k0+6]), 0.f);
        hv[7] = fmaxf(fmaf(v1.w, scl[k0+7], shf[k0+7]), 0.f);
        int kb = s*16 + bkk;
        #pragma unroll
        for (int j = 0; j < 4; j++){
            int col = bc4 + j;
            bb[j] = (col < COUT_) ? __ldg(Mw + (size_t)kb*COUT_ + col) : 0.f;
        }
    };
    auto STORE = [&](int p){
        float h0,l0,h1,l1,h2,l2,h3,l3,h4,l4,h5,l5,h6,l6,h7,l7;
        split_bf(hv[0],h0,l0); split_bf(hv[1],h1,l1); split_bf(hv[2],h2,l2); split_bf(hv[3],h3,l3);
        split_bf(hv[4],h4,l4); split_bf(hv[5],h5,l5); split_bf(hv[6],h6,l6); split_bf(hv[7],h7,l7);
        unsigned short* ap = Ahs + (size_t)p*3072 + am*24 + akh*8;
        unsigned short* alp = Als + (size_t)p*3072 + am*24 + akh*8;
        *(uint4*)ap  = make_uint4(pack2(h0,h1), pack2(h2,h3), pack2(h4,h5), pack2(h6,h7));
        *(uint4*)alp = make_uint4(pack2(l0,l1), pack2(l2,l3), pack2(l4,l5), pack2(l6,l7));
        split_bf(bb[0],h0,l0); split_bf(bb[1],h1,l1); split_bf(bb[2],h2,l2); split_bf(bb[3],h3,l3);
        unsigned short* bp = Bhs + (size_t)p*1152 + bkk*72 + bc4;
        unsigned short* blp2 = Bls + (size_t)p*1152 + bkk*72 + bc4;
        *(uint2*)bp   = make_uint2(pack2(h0,h1), pack2(h2,h3));
        *(uint2*)blp2 = make_uint2(pack2(l0,l1), pack2(l2,l3));
    };

    LOAD(0); STORE(0);
    __syncthreads();

    for (int s = 0; s < 16; s++){
        int p = s & 1;
        if (s < 15) LOAD(s+1);

        unsigned ah[2][4], al[2][4], bh[2][4], bl[2][4];
        #pragma unroll
        for (int mf = 0; mf < 2; mf++){
            ldsm_x4(ah[mf], ah_b[p] + a_off[mf]);
            ldsm_x4(al[mf], al_b[p] + a_off[mf]);
        }
        #pragma unroll
        for (int nfp = 0; nfp < 2; nfp++){
            ldsm_x4_t(bh[nfp], bh_b[p] + b_off[nfp]);
            ldsm_x4_t(bl[nfp], bl_b[p] + b_off[nfp]);
        }
        #pragma unroll
        for (int nf = 0; nf < 4; nf++){
            const unsigned* bhp = &bh[nf>>1][(nf&1)*2];
            const unsigned* blp = &bl[nf>>1][(nf&1)*2];
            #pragma unroll
            for (int mf = 0; mf < 2; mf++){
                mma_bf16(acc[mf][nf], ah[mf], bhp);
                mma_bf16(acc[mf][nf], al[mf], bhp);
                mma_bf16(acc[mf][nf], ah[mf], blp);
            }
        }
        __syncthreads();
        if (s < 15){ STORE(p ^ 1); __syncthreads(); }
    }

    // epilogue: logits to smem (aliased), log-softmax over 40 cols
    #pragma unroll
    for (int mf = 0; mf < 2; mf++){
        #pragma unroll
        for (int nf = 0; nf < 4; nf++){
            int m = wm*32 + mf*16 + g;
            int nl = wn*32 + nf*8 + 2*t;
            if (nl < COUT_){
                float mb = __ldg(Mb + nl);
                lgs[m*48 + nl]     = acc[mf][nf][0] + mb;
                lgs[(m+8)*48 + nl] = acc[mf][nf][2] + mb;
            }
            if (nl + 1 < COUT_){
                float mb = __ldg(Mb + nl + 1);
                lgs[m*48 + nl + 1]     = acc[mf][nf][1] + mb;
                lgs[(m+8)*48 + nl + 1] = acc[mf][nf][3] + mb;
            }
        }
    }
    __syncthreads();
    if (tid < 128){
        float mx = -1e30f;
        #pragma unroll 8
        for (int o = 0; o < COUT_; o++) mx = fmaxf(mx, lgs[tid*48 + o]);
        float s = 0.f;
        #pragma unroll 8
        for (int o = 0; o < COUT_; o++) s += expf(lgs[tid*48 + o] - mx);
        lgz[tid] = mx + logf(s);
    }
    __syncthreads();
    for (int idx = tid; idx < 128*COUT_; idx += 256){
        int r = idx / COUT_;
        int c = idx - r*COUT_;
        out[(size_t)(m0+r)*COUT_ + idx - r*COUT_ + c*0] = lgs[r*48 + c] - lgz[r];
    }
}

// ---------------- launch ----------------
extern "C" void kernel_launch(void* const* d_in, const int* in_sizes, int n_in,
                              void* d_out, int out_size){
    const float* X     = (const float*)d_in[0];
    const float* La    = (const float*)d_in[1];
    const float* U     = (const float*)d_in[2];
    const float* eW1   = (const float*)d_in[3];
    const float* eb1   = (const float*)d_in[4];
    const float* eW2   = (const float*)d_in[5];
    const float* eb2   = (const float*)d_in[6];
    const float* eW3   = (const float*)d_in[7];
    const float* eb3   = (const float*)d_in[8];
    const float* gW1   = (const float*)d_in[9];
    const float* gb1   = (const float*)d_in[10];
    const float* gW2   = (const float*)d_in[11];
    const float* gb2   = (const float*)d_in[12];
    const float* Ww    = (const float*)d_in[13];
    const float* Wb    = (const float*)d_in[14];
    const float* gamma = (const float*)d_in[15];
    const float* beta  = (const float*)d_in[16];
    const float* Mw    = (const float*)d_in[17];
    const float* Mb    = (const float*)d_in[18];

    float* outF   = (float*)d_out;
    float* logits = outF;                              // [N, COUT]
    float* hidden = outF + (size_t)N_*COUT_;           // [N, HID]

    lutgate_kernel<<<dim3(TLUT/128, E_), 128>>>(eW1, eb1, eW2, eb2, eW3, eb3,
                                                La, gW1, gb1, gW2, gb2);
    vs_kernel<<<1024, 256>>>(U);
    gemmD_tc<<<dim3(CIN_/64, 2, NS2), 256>>>(U, X);
    reduceM_kernel<<<dim3(K_, 2), 256>>>();            // launch #4 -> profiled
    pgemm_tc<<<dim3(HID_/64, 4, PZ), 256>>>(Ww);
    reduceP_kernel<<<K_, 256>>>();
    gemmE_tc<<<dim3(N_/128, HID_/64), 256>>>(U, Wb, hidden);
    bn_final<<<1, HID_>>>(gamma, beta);
    head_tc<<<N_/128, 256>>>(hidden, Mw, Mb, logits);
}